// round 13
// baseline (speedup 1.0000x reference)
#include <cuda_runtime.h>
#include <cuda_fp16.h>
#include <cstdint>

#define F_DIM   128
#define FM_DIM  16
#define DIN     257
#define DH      514
#define UIN     144
#define UH      256
#define HID     128
#define T_OUT   12
#define SP      520     // padded row stride for Pd/Ps in HALVES (1040B, 16B-aligned)

#define MAXN 50048
#define MAXE 800000
#define MAXG 1024

// ---------------- scratch (no allocations allowed) ----------------
__device__ __align__(256) float  g_h0[MAXN * F_DIM];
__device__ __align__(256) float  g_h1[MAXN * F_DIM];
__device__ __align__(256) float  g_en2[MAXE];      // norm2, dst-sorted order
__device__ __align__(256) float  g_en2r[MAXE];     // norm2, raw edge order
__device__ __align__(256) float  g_agg[MAXN * FM_DIM];
__device__ __align__(256) float  g_pooled[MAXG * HID];
__device__ __align__(256) __half g_Pd[MAXN * SP];  // h @ W1[0:128] + b1   (fp16)
__device__ __align__(256) __half g_Ps[MAXN * SP];  // h @ W1[128:256]      (fp16)
__device__ __align__(256) int    g_cur[MAXN];      // scan cursor
__device__ __align__(256) int    g_es[MAXE];       // sorted src
__device__ __align__(256) int    g_ed[MAXE];       // sorted dst

// ---------------- helpers ----------------
__device__ __forceinline__ float swishf(float x) {
    return __fdividef(x, 1.0f + __expf(-x));
}

typedef unsigned long long ull;

__device__ __forceinline__ void fma2(ull& d, ull a, ull b) {
    asm("fma.rn.f32x2 %0, %1, %2, %0;" : "+l"(d) : "l"(a), "l"(b));
}
__device__ __forceinline__ ull pack2(float x) {
    ull r;
    asm("mov.b64 %0, {%1, %1};" : "=l"(r) : "f"(x));
    return r;
}
__device__ __forceinline__ void unpack2(ull v, float& lo, float& hi) {
    asm("mov.b64 {%0, %1}, %2;" : "=f"(lo), "=f"(hi) : "l"(v));
}

// ---------------- small kernels ----------------
__global__ void zero_kernel(float* p, int n) {
    int i = blockIdx.x * blockDim.x + threadIdx.x;
    if (i < n) p[i] = 0.0f;
}

// h init (+ zero the sort cursor, fused to save a launch)
__global__ void init_h_kernel(const void* zptr, const float* __restrict__ emb,
                              float* __restrict__ h, int* __restrict__ cur, int N) {
    int i = blockIdx.x * blockDim.x + threadIdx.x;
    if (i < N) cur[i] = 0;
    if (i >= N * F_DIM) return;
    int node = i / F_DIM, f = i % F_DIM;
    const int* z32 = (const int*)zptr;
    bool is64 = (z32[1] == 0) && (z32[3] == 0) && (z32[5] == 0);
    long long zv = is64 ? ((const long long*)zptr)[node] : (long long)z32[node];
    int e = (zv == 1) ? 0 : (int)(zv - 5);
    h[i] = emb[e * F_DIM + f];
}

__global__ void norm2_kernel(const float* __restrict__ pos,
                             const int* __restrict__ ei,
                             float* __restrict__ norm2, int E) {
    int e = blockIdx.x * blockDim.x + threadIdx.x;
    if (e >= E) return;
    int s = ei[e], d = ei[E + e];
    float dx = pos[s * 3 + 0] - pos[d * 3 + 0];
    float dy = pos[s * 3 + 1] - pos[d * 3 + 1];
    float dz = pos[s * 3 + 2] - pos[d * 3 + 2];
    norm2[e] = dx * dx + dy * dy + dz * dz;
}

// ---------------- counting sort of edges by dst ----------------
__global__ void hist_kernel(const int* __restrict__ ei, int* __restrict__ cnt, int E) {
    int e = blockIdx.x * blockDim.x + threadIdx.x;
    if (e < E) atomicAdd(&cnt[ei[E + e]], 1);
}

__global__ void scan_kernel(int* __restrict__ cnt, int* __restrict__ cur, int N) {
    __shared__ int sdata[1024];
    __shared__ int carry_s;
    if (threadIdx.x == 0) carry_s = 0;
    __syncthreads();
    for (int base = 0; base < N; base += 1024) {
        int i = base + threadIdx.x;
        int v = (i < N) ? cnt[i] : 0;
        sdata[threadIdx.x] = v;
        __syncthreads();
        for (int ofs = 1; ofs < 1024; ofs <<= 1) {
            int t = (threadIdx.x >= ofs) ? sdata[threadIdx.x - ofs] : 0;
            __syncthreads();
            sdata[threadIdx.x] += t;
            __syncthreads();
        }
        int excl = sdata[threadIdx.x] - v + carry_s;
        if (i < N) cur[i] = excl;
        __syncthreads();
        if (threadIdx.x == 0) carry_s += sdata[1023];
        __syncthreads();
    }
}

__global__ void scatter_kernel(const int* __restrict__ ei,
                               const float* __restrict__ en2r,
                               int* __restrict__ cur,
                               int* __restrict__ es, int* __restrict__ ed,
                               float* __restrict__ en2, int E) {
    int e = blockIdx.x * blockDim.x + threadIdx.x;
    if (e >= E) return;
    int s = ei[e], d = ei[E + e];
    int p = atomicAdd(&cur[d], 1);
    es[p] = s; ed[p] = d;
    en2[p] = en2r[e];
}

// ---------------- per-node pre-GEMM: P = h @ W (+bias), fp16 out ----------
// 128-node x 128-col tile, 8x8 output per thread (f32x2), 2 CTA/SM.
// Slice (y=0,z=0) also zeroes agg (fused; kernel boundary orders it vs edge).
#define PREP_SMEM_BYTES ((128 * 132 + 8 * 132) * 4)

__global__ __launch_bounds__(256)
void prep_gemm_kernel(const float* __restrict__ h, const float* __restrict__ W1,
                      const float* __restrict__ bias,
                      __half* __restrict__ Pd, __half* __restrict__ Ps,
                      float* __restrict__ agg, int N) {
    extern __shared__ float sm[];
    float* sH = sm;              // 128 x 132
    float* sB = sH + 128 * 132;  // 8 x 132

    const int tid = threadIdx.x;
    const int n0 = blockIdx.x * 128;
    const int c0 = blockIdx.y * 128;
    const int which = blockIdx.z;
    const float* W = W1 + (size_t)which * 128 * DH;
    __half* P = which ? Ps : Pd;

    if (blockIdx.y == 0 && blockIdx.z == 0) {
        for (int i = blockIdx.x * 256 + tid; i < N * FM_DIM; i += gridDim.x * 256)
            agg[i] = 0.0f;
    }

    // load h tile [128 x 128] as float4
    for (int idx = tid; idx < 128 * 32; idx += 256) {
        int r = idx >> 5, c4 = (idx & 31) * 4;
        int node = n0 + r;
        float4 v = make_float4(0.f, 0.f, 0.f, 0.f);
        if (node < N) v = *(const float4*)(h + (size_t)node * F_DIM + c4);
        *(float4*)(sH + r * 132 + c4) = v;
    }
    __syncthreads();

    const int ty = tid >> 4, tx = tid & 15;
    const int r0 = ty * 8, ct = tx * 8;

    ull C[8][4];
    #pragma unroll
    for (int i = 0; i < 8; i++)
        #pragma unroll
        for (int j = 0; j < 4; j++) C[i][j] = 0;

    for (int k0 = 0; k0 < 128; k0 += 8) {
        #pragma unroll
        for (int it = 0; it < 4; it++) {
            int t = tid + it * 256;
            int kk = t >> 7, c = t & 127;
            int col = c0 + c;
            sB[kk * 132 + c] = (col < DH) ? W[(size_t)(k0 + kk) * DH + col] : 0.0f;
        }
        __syncthreads();
        #pragma unroll
        for (int kk = 0; kk < 8; kk++) {
            const float* bp = sB + kk * 132 + ct;
            ull b0 = *(const ull*)(bp);
            ull b1 = *(const ull*)(bp + 2);
            ull b2v = *(const ull*)(bp + 4);
            ull b3 = *(const ull*)(bp + 6);
            #pragma unroll
            for (int i = 0; i < 8; i++) {
                ull aa = pack2(sH[(r0 + i) * 132 + k0 + kk]);
                fma2(C[i][0], aa, b0); fma2(C[i][1], aa, b1);
                fma2(C[i][2], aa, b2v); fma2(C[i][3], aa, b3);
            }
        }
        __syncthreads();
    }

    #pragma unroll
    for (int i = 0; i < 8; i++) {
        int node = n0 + r0 + i;
        if (node >= N) continue;
        float v[8];
        unpack2(C[i][0], v[0], v[1]); unpack2(C[i][1], v[2], v[3]);
        unpack2(C[i][2], v[4], v[5]); unpack2(C[i][3], v[6], v[7]);
        int col0 = c0 + ct;
        __half* prow = P + (size_t)node * SP + col0;
        #pragma unroll
        for (int j = 0; j < 8; j++)
            v[j] += (which == 0 && col0 + j < DH) ? bias[col0 + j] : 0.0f;
        if (col0 + 8 <= DH) {
            __half2 h01 = __floats2half2_rn(v[0], v[1]);
            __half2 h23 = __floats2half2_rn(v[2], v[3]);
            __half2 h45 = __floats2half2_rn(v[4], v[5]);
            __half2 h67 = __floats2half2_rn(v[6], v[7]);
            uint4 st;
            st.x = *(unsigned*)&h01; st.y = *(unsigned*)&h23;
            st.z = *(unsigned*)&h45; st.w = *(unsigned*)&h67;
            *(uint4*)prow = st;
        } else {
            #pragma unroll
            for (int j = 0; j < 8; j++)
                if (col0 + j < SP)
                    prow[j] = __float2half_rn((col0 + j < DH) ? v[j] : 0.0f);
        }
    }
}

// ---------------- edge phase: 1 edge/thread, register-resident -----------
#define EDGE_SMEM_BYTES ((516 * 16 + 516) * 4)

__global__ __launch_bounds__(256)
void edge_kernel(const __half* __restrict__ Pd, const __half* __restrict__ Ps,
                 const float* __restrict__ Wn,   // W1 row 256 (norm2 row)
                 const float* __restrict__ W2, const float* __restrict__ b2,
                 const int* __restrict__ es, const int* __restrict__ ed,
                 const float* __restrict__ en2,
                 float* __restrict__ agg, int E) {
    extern __shared__ float sm[];
    float* sW2 = sm;               // 516 x 16 (rows >=514 zero)
    float* sWn = sW2 + 516 * 16;   // 516 (pad zero)

    const int tid = threadIdx.x;
    for (int i = tid; i < 516 * 16; i += 256) {
        int k = i >> 4;
        sW2[i] = (k < DH) ? W2[i] : 0.0f;
    }
    for (int i = tid; i < 516; i += 256)
        sWn[i] = (i < DH) ? Wn[i] : 0.0f;
    __syncthreads();

    const int e = blockIdx.x * 256 + tid;
    const bool act = (e < E);
    int d = 0, s = 0;
    float n2 = 0.0f;
    if (act) { d = ed[e]; s = es[e]; n2 = en2[e]; }
    const __half* pd = Pd + (size_t)d * SP;
    const __half* ps = Ps + (size_t)s * SP;

    ull m[8];
    #pragma unroll
    for (int j = 0; j < 8; j++) m[j] = 0;

    // prefetch chunk 0 (4 slots of 8 halves per array)
    uint4 bpd[4], bps[4];
    #pragma unroll
    for (int j = 0; j < 4; j++) {
        bpd[j] = *(const uint4*)(pd + j * 8);
        bps[j] = *(const uint4*)(ps + j * 8);
    }

    for (int c = 0; c < 16; c++) {
        const int k0 = c * 32;
        #pragma unroll
        for (int j = 0; j < 4; j++) {
            const __half2* ha = (const __half2*)&bpd[j];
            const __half2* hb = (const __half2*)&bps[j];
            float2 f0 = __half22float2(__hadd2(ha[0], hb[0]));
            float2 f1 = __half22float2(__hadd2(ha[1], hb[1]));
            float2 f2 = __half22float2(__hadd2(ha[2], hb[2]));
            float2 f3 = __half22float2(__hadd2(ha[3], hb[3]));
            // refill this slot for the next chunk (covered by GEMM below)
            if (c < 15) {
                bpd[j] = *(const uint4*)(pd + k0 + 32 + j * 8);
                bps[j] = *(const uint4*)(ps + k0 + 32 + j * 8);
            }
            const int kb = k0 + j * 8;
            float4 wl = *(const float4*)(sWn + kb);
            float4 wh = *(const float4*)(sWn + kb + 4);
            float x[8];
            x[0] = fmaf(n2, wl.x, f0.x); x[1] = fmaf(n2, wl.y, f0.y);
            x[2] = fmaf(n2, wl.z, f1.x); x[3] = fmaf(n2, wl.w, f1.y);
            x[4] = fmaf(n2, wh.x, f2.x); x[5] = fmaf(n2, wh.y, f2.y);
            x[6] = fmaf(n2, wh.z, f3.x); x[7] = fmaf(n2, wh.w, f3.y);
            #pragma unroll
            for (int q = 0; q < 8; q++) {
                float sw = swishf(x[q]);
                ull aa = pack2(sw);
                const float* wp = sW2 + (kb + q) * 16;
                float4 w0 = *(const float4*)(wp);
                float4 w1 = *(const float4*)(wp + 4);
                float4 w2v = *(const float4*)(wp + 8);
                float4 w3 = *(const float4*)(wp + 12);
                fma2(m[0], aa, *(ull*)&w0);  fma2(m[1], aa, *((ull*)&w0 + 1));
                fma2(m[2], aa, *(ull*)&w1);  fma2(m[3], aa, *((ull*)&w1 + 1));
                fma2(m[4], aa, *(ull*)&w2v); fma2(m[5], aa, *((ull*)&w2v + 1));
                fma2(m[6], aa, *(ull*)&w3);  fma2(m[7], aa, *((ull*)&w3 + 1));
            }
        }
    }

    // tail k = 512..513
    {
        uint2 va = *(const uint2*)(pd + 512);
        uint2 vb = *(const uint2*)(ps + 512);
        __half2 a0 = *(__half2*)&va.x, b0 = *(__half2*)&vb.x;
        float2 f = __half22float2(__hadd2(a0, b0));
        float xt[2];
        xt[0] = fmaf(n2, sWn[512], f.x);
        xt[1] = fmaf(n2, sWn[513], f.y);
        #pragma unroll
        for (int q = 0; q < 2; q++) {
            float sw = swishf(xt[q]);
            ull aa = pack2(sw);
            const float* wp = sW2 + (512 + q) * 16;
            float4 w0 = *(const float4*)(wp);
            float4 w1 = *(const float4*)(wp + 4);
            float4 w2v = *(const float4*)(wp + 8);
            float4 w3 = *(const float4*)(wp + 12);
            fma2(m[0], aa, *(ull*)&w0);  fma2(m[1], aa, *((ull*)&w0 + 1));
            fma2(m[2], aa, *(ull*)&w1);  fma2(m[3], aa, *((ull*)&w1 + 1));
            fma2(m[4], aa, *(ull*)&w2v); fma2(m[5], aa, *((ull*)&w2v + 1));
            fma2(m[6], aa, *(ull*)&w3);  fma2(m[7], aa, *((ull*)&w3 + 1));
        }
    }

    // epilogue: swish(m2 + b2) -> atomic scatter
    if (act) {
        float* ap = agg + (size_t)d * FM_DIM;
        #pragma unroll
        for (int j = 0; j < 8; j++) {
            float lo, hi;
            unpack2(m[j], lo, hi);
            atomicAdd(ap + 2 * j,     swishf(lo + b2[2 * j]));
            atomicAdd(ap + 2 * j + 1, swishf(hi + b2[2 * j + 1]));
        }
    }
}

// ---------------- fused node update ----------------
#define SU_STR 148
#define NODE_SMEM_BYTES ((64 * SU_STR + 64 * 132 + 8 * 132) * 4)

__global__ __launch_bounds__(256)
void node_update_kernel(const float* __restrict__ h,
                        const float* __restrict__ agg,
                        const float* __restrict__ W1, const float* __restrict__ b1,
                        const float* __restrict__ W2, const float* __restrict__ b2,
                        float* __restrict__ hout, int N) {
    extern __shared__ float sm[];
    float* sU  = sm;
    float* sU1 = sU + 64 * SU_STR;
    float* sB  = sU1 + 64 * 132;

    const int tid = threadIdx.x;
    const int n0 = blockIdx.x * 64;

    for (int idx = tid; idx < 64 * UIN; idx += 256) {
        int r = idx / UIN, c = idx % UIN;
        int node = n0 + r;
        float v = 0.0f;
        if (node < N)
            v = (c < FM_DIM) ? agg[(size_t)node * FM_DIM + c]
                             : h[(size_t)node * F_DIM + (c - FM_DIM)];
        sU[r * SU_STR + c] = v;
    }
    __syncthreads();

    const int ty = tid >> 4, tx = tid & 15;
    const int r0 = ty * 4, ct = tx * 8;

    float C2[4][8];
    #pragma unroll
    for (int i = 0; i < 4; i++)
        #pragma unroll
        for (int j = 0; j < 8; j++) C2[i][j] = 0.0f;

    for (int c0 = 0; c0 < UH; c0 += 128) {
        float C1[4][8];
        #pragma unroll
        for (int i = 0; i < 4; i++)
            #pragma unroll
            for (int j = 0; j < 8; j++) C1[i][j] = 0.0f;

        for (int k0 = 0; k0 < UIN; k0 += 8) {
            #pragma unroll
            for (int it = 0; it < 4; it++) {
                int t = tid + it * 256;
                int kk = t >> 7, c = t & 127;
                sB[kk * 132 + c] = W1[(size_t)(k0 + kk) * UH + c0 + c];
            }
            __syncthreads();
            #pragma unroll
            for (int kk = 0; kk < 8; kk++) {
                float4 b0 = *(const float4*)(sB + kk * 132 + ct);
                float4 b1v = *(const float4*)(sB + kk * 132 + ct + 4);
                #pragma unroll
                for (int i = 0; i < 4; i++) {
                    float a = sU[(r0 + i) * SU_STR + k0 + kk];
                    C1[i][0] += a * b0.x; C1[i][1] += a * b0.y;
                    C1[i][2] += a * b0.z; C1[i][3] += a * b0.w;
                    C1[i][4] += a * b1v.x; C1[i][5] += a * b1v.y;
                    C1[i][6] += a * b1v.z; C1[i][7] += a * b1v.w;
                }
            }
            __syncthreads();
        }
        #pragma unroll
        for (int i = 0; i < 4; i++)
            #pragma unroll
            for (int j = 0; j < 8; j++)
                sU1[(r0 + i) * 132 + ct + j] = swishf(C1[i][j] + b1[c0 + ct + j]);
        __syncthreads();

        for (int k0 = 0; k0 < 128; k0 += 8) {
            #pragma unroll
            for (int it = 0; it < 4; it++) {
                int t = tid + it * 256;
                int kk = t >> 7, c = t & 127;
                sB[kk * 132 + c] = W2[(size_t)(c0 + k0 + kk) * F_DIM + c];
            }
            __syncthreads();
            #pragma unroll
            for (int kk = 0; kk < 8; kk++) {
                float4 b0 = *(const float4*)(sB + kk * 132 + ct);
                float4 b1v = *(const float4*)(sB + kk * 132 + ct + 4);
                #pragma unroll
                for (int i = 0; i < 4; i++) {
                    float a = sU1[(r0 + i) * 132 + k0 + kk];
                    C2[i][0] += a * b0.x; C2[i][1] += a * b0.y;
                    C2[i][2] += a * b0.z; C2[i][3] += a * b0.w;
                    C2[i][4] += a * b1v.x; C2[i][5] += a * b1v.y;
                    C2[i][6] += a * b1v.z; C2[i][7] += a * b1v.w;
                }
            }
            __syncthreads();
        }
    }

    #pragma unroll
    for (int i = 0; i < 4; i++) {
        int node = n0 + r0 + i;
        if (node < N) {
            #pragma unroll
            for (int j = 0; j < 8; j++)
                hout[(size_t)node * F_DIM + ct + j] =
                    C2[i][j] + b2[ct + j] + sU[(r0 + i) * SU_STR + FM_DIM + ct + j];
        }
    }
}

// ---------------- projection + sorted-batch pooling ----------------
#define PROJ_SMEM_BYTES ((64 * 132 * 2 + 8 * 132) * 4 + 64 * 4)

__global__ __launch_bounds__(256)
void proj_pool_kernel(const float* __restrict__ h,
                      const int* __restrict__ batch,
                      const float* __restrict__ Wp1, const float* __restrict__ bp1,
                      const float* __restrict__ Wp2, const float* __restrict__ bp2,
                      float* __restrict__ pooled, int N) {
    extern __shared__ float sm[];
    float* sH = sm;
    float* sG = sH + 64 * 132;
    float* sB = sG + 64 * 132;
    int* sBatch = (int*)(sB + 8 * 132);

    const int tid = threadIdx.x;
    const int n0 = blockIdx.x * 64;

    for (int idx = tid; idx < 64 * HID; idx += 256) {
        int r = idx >> 7, c = idx & 127;
        int node = n0 + r;
        sH[r * 132 + c] = (node < N) ? h[(size_t)node * F_DIM + c] : 0.0f;
    }
    if (tid < 64) {
        int node = n0 + tid;
        sBatch[tid] = (node < N) ? batch[node] : -1;
    }
    __syncthreads();

    const int ty = tid >> 4, tx = tid & 15;
    const int r0 = ty * 4, ct = tx * 8;

    float C1[4][8];
    #pragma unroll
    for (int i = 0; i < 4; i++)
        #pragma unroll
        for (int j = 0; j < 8; j++) C1[i][j] = 0.0f;

    for (int k0 = 0; k0 < HID; k0 += 8) {
        #pragma unroll
        for (int it = 0; it < 4; it++) {
            int t = tid + it * 256;
            int kk = t >> 7, c = t & 127;
            sB[kk * 132 + c] = Wp1[(size_t)(k0 + kk) * HID + c];
        }
        __syncthreads();
        #pragma unroll
        for (int kk = 0; kk < 8; kk++) {
            float4 b0 = *(const float4*)(sB + kk * 132 + ct);
            float4 b1v = *(const float4*)(sB + kk * 132 + ct + 4);
            #pragma unroll
            for (int i = 0; i < 4; i++) {
                float a = sH[(r0 + i) * 132 + k0 + kk];
                C1[i][0] += a * b0.x; C1[i][1] += a * b0.y;
                C1[i][2] += a * b0.z; C1[i][3] += a * b0.w;
                C1[i][4] += a * b1v.x; C1[i][5] += a * b1v.y;
                C1[i][6] += a * b1v.z; C1[i][7] += a * b1v.w;
            }
        }
        __syncthreads();
    }
    #pragma unroll
    for (int i = 0; i < 4; i++)
        #pragma unroll
        for (int j = 0; j < 8; j++)
            sG[(r0 + i) * 132 + ct + j] = swishf(C1[i][j] + bp1[ct + j]);
    __syncthreads();

    float C2[4][8];
    #pragma unroll
    for (int i = 0; i < 4; i++)
        #pragma unroll
        for (int j = 0; j < 8; j++) C2[i][j] = 0.0f;

    for (int k0 = 0; k0 < HID; k0 += 8) {
        #pragma unroll
        for (int it = 0; it < 4; it++) {
            int t = tid + it * 256;
            int kk = t >> 7, c = t & 127;
            sB[kk * 132 + c] = Wp2[(size_t)(k0 + kk) * HID + c];
        }
        __syncthreads();
        #pragma unroll
        for (int kk = 0; kk < 8; kk++) {
            float4 b0 = *(const float4*)(sB + kk * 132 + ct);
            float4 b1v = *(const float4*)(sB + kk * 132 + ct + 4);
            #pragma unroll
            for (int i = 0; i < 4; i++) {
                float a = sG[(r0 + i) * 132 + k0 + kk];
                C2[i][0] += a * b0.x; C2[i][1] += a * b0.y;
                C2[i][2] += a * b0.z; C2[i][3] += a * b0.w;
                C2[i][4] += a * b1v.x; C2[i][5] += a * b1v.y;
                C2[i][6] += a * b1v.z; C2[i][7] += a * b1v.w;
            }
        }
        __syncthreads();
    }
    #pragma unroll
    for (int i = 0; i < 4; i++)
        #pragma unroll
        for (int j = 0; j < 8; j++)
            sH[(r0 + i) * 132 + ct + j] = C2[i][j] + bp2[ct + j];
    __syncthreads();

    if (tid < HID) {
        int col = tid;
        int g = sBatch[0];
        float acc = 0.0f;
        for (int r = 0; r < 64; r++) {
            int gg = sBatch[r];
            if (gg != g) {
                if (g >= 0) atomicAdd(&pooled[(size_t)g * HID + col], acc);
                acc = 0.0f;
                g = gg;
            }
            acc += sH[r * 132 + col];
        }
        if (g >= 0) atomicAdd(&pooled[(size_t)g * HID + col], acc);
    }
}

// ---------------- readout ----------------
#define RO_SMEM_BYTES ((64 * 132 * 2 + 8 * 132) * 4)

__global__ __launch_bounds__(256)
void readout_kernel(const float* __restrict__ pooled,
                    const float* __restrict__ Wr1, const float* __restrict__ br1,
                    const float* __restrict__ Wr2, const float* __restrict__ br2,
                    float* __restrict__ out, int G) {
    extern __shared__ float sm[];
    float* sP = sm;
    float* sR = sP + 64 * 132;
    float* sB = sR + 64 * 132;

    const int tid = threadIdx.x;
    const int g0 = blockIdx.x * 64;

    for (int idx = tid; idx < 64 * HID; idx += 256) {
        int r = idx >> 7, c = idx & 127;
        int g = g0 + r;
        sP[r * 132 + c] = (g < G) ? pooled[(size_t)g * HID + c] : 0.0f;
    }
    __syncthreads();

    const int ty = tid >> 4, tx = tid & 15;
    const int r0 = ty * 4, ct = tx * 8;

    float C1[4][8];
    #pragma unroll
    for (int i = 0; i < 4; i++)
        #pragma unroll
        for (int j = 0; j < 8; j++) C1[i][j] = 0.0f;

    for (int k0 = 0; k0 < HID; k0 += 8) {
        #pragma unroll
        for (int it = 0; it < 4; it++) {
            int t = tid + it * 256;
            int kk = t >> 7, c = t & 127;
            sB[kk * 132 + c] = Wr1[(size_t)(k0 + kk) * HID + c];
        }
        __syncthreads();
        #pragma unroll
        for (int kk = 0; kk < 8; kk++) {
            float4 b0 = *(const float4*)(sB + kk * 132 + ct);
            float4 b1v = *(const float4*)(sB + kk * 132 + ct + 4);
            #pragma unroll
            for (int i = 0; i < 4; i++) {
                float a = sP[(r0 + i) * 132 + k0 + kk];
                C1[i][0] += a * b0.x; C1[i][1] += a * b0.y;
                C1[i][2] += a * b0.z; C1[i][3] += a * b0.w;
                C1[i][4] += a * b1v.x; C1[i][5] += a * b1v.y;
                C1[i][6] += a * b1v.z; C1[i][7] += a * b1v.w;
            }
        }
        __syncthreads();
    }
    #pragma unroll
    for (int i = 0; i < 4; i++)
        #pragma unroll
        for (int j = 0; j < 8; j++)
            sR[(r0 + i) * 132 + ct + j] = swishf(C1[i][j] + br1[ct + j]);
    __syncthreads();

    for (int idx = tid; idx < 64 * T_OUT; idx += 256) {
        int e = idx / T_OUT, t = idx % T_OUT;
        int g = g0 + e;
        if (g < G) {
            float acc = br2[t];
            #pragma unroll 4
            for (int k = 0; k < HID; k++)
                acc += sR[e * 132 + k] * Wr2[(size_t)k * T_OUT + t];
            out[(size_t)g * T_OUT + t] = acc;
        }
    }
}

// ---------------- launch ----------------
extern "C" void kernel_launch(void* const* d_in, const int* in_sizes, int n_in,
                              void* d_out, int out_size) {
    const float* pos    = (const float*)d_in[0];
    const void*  zptr   = d_in[1];
    const int*   ei     = (const int*)d_in[2];
    const int*   batch  = (const int*)d_in[3];
    const float* emb    = (const float*)d_in[4];
    const float* W_msg1 = (const float*)d_in[5];
    const float* b_msg1 = (const float*)d_in[6];
    const float* W_msg2 = (const float*)d_in[7];
    const float* b_msg2 = (const float*)d_in[8];
    const float* W_up1  = (const float*)d_in[9];
    const float* b_up1  = (const float*)d_in[10];
    const float* W_up2  = (const float*)d_in[11];
    const float* b_up2  = (const float*)d_in[12];
    const float* Wp1    = (const float*)d_in[13];
    const float* bp1    = (const float*)d_in[14];
    const float* Wp2    = (const float*)d_in[15];
    const float* bp2    = (const float*)d_in[16];
    const float* Wr1    = (const float*)d_in[17];
    const float* br1    = (const float*)d_in[18];
    const float* Wr2    = (const float*)d_in[19];
    const float* br2    = (const float*)d_in[20];
    float* out = (float*)d_out;

    const int N = in_sizes[0] / 3;
    const int E = in_sizes[2] / 2;
    const int L = in_sizes[5] / (DIN * DH);
    const int G = out_size / T_OUT;

    float *h0, *h1, *aggp, *pooledp, *en2p, *en2rp;
    __half *pdp, *psp;
    int *curp, *esp, *edp;
    cudaGetSymbolAddress((void**)&h0, g_h0);
    cudaGetSymbolAddress((void**)&h1, g_h1);
    cudaGetSymbolAddress((void**)&aggp, g_agg);
    cudaGetSymbolAddress((void**)&pooledp, g_pooled);
    cudaGetSymbolAddress((void**)&en2p, g_en2);
    cudaGetSymbolAddress((void**)&en2rp, g_en2r);
    cudaGetSymbolAddress((void**)&pdp, g_Pd);
    cudaGetSymbolAddress((void**)&psp, g_Ps);
    cudaGetSymbolAddress((void**)&curp, g_cur);
    cudaGetSymbolAddress((void**)&esp, g_es);
    cudaGetSymbolAddress((void**)&edp, g_ed);

    cudaFuncSetAttribute(edge_kernel,
                         cudaFuncAttributeMaxDynamicSharedMemorySize, EDGE_SMEM_BYTES);
    cudaFuncSetAttribute(prep_gemm_kernel,
                         cudaFuncAttributeMaxDynamicSharedMemorySize, PREP_SMEM_BYTES);
    cudaFuncSetAttribute(node_update_kernel,
                         cudaFuncAttributeMaxDynamicSharedMemorySize, NODE_SMEM_BYTES);
    cudaFuncSetAttribute(proj_pool_kernel,
                         cudaFuncAttributeMaxDynamicSharedMemorySize, PROJ_SMEM_BYTES);
    cudaFuncSetAttribute(readout_kernel,
                         cudaFuncAttributeMaxDynamicSharedMemorySize, RO_SMEM_BYTES);

    const int nblk = (N + 63) / 64;
    const dim3 prep_grid((N + 127) / 128, 5, 2);

    // ---- layer 0 on RAW edge order (no sort dependency); edge L0 is the
    // 4th launch, which is the one ncu -s 5 -c 1 captures. ----
    init_h_kernel<<<(N * F_DIM + 255) / 256, 256>>>(zptr, emb, h0, curp, N);   // 0
    norm2_kernel<<<(E + 255) / 256, 256>>>(pos, ei, en2rp, E);                 // 1
    {
        const float* W1l = W_msg1;
        prep_gemm_kernel<<<prep_grid, 256, PREP_SMEM_BYTES>>>(                 // 2
            h0, W1l, b_msg1, pdp, psp, aggp, N);
        edge_kernel<<<(E + 255) / 256, 256, EDGE_SMEM_BYTES>>>(                // 3
            pdp, psp, W1l + (size_t)256 * DH,
            W_msg2, b_msg2, ei, ei + E, en2rp, aggp, E);
    }
    // ---- counting sort for layers 1..L-1 (overlap-free, same stream) ----
    hist_kernel<<<(E + 255) / 256, 256>>>(ei, curp, E);                        // 4
    scan_kernel<<<1, 1024>>>(curp, curp, N);                                   // 5
    scatter_kernel<<<(E + 255) / 256, 256>>>(ei, en2rp, curp, esp, edp, en2p, E); // 6
    node_update_kernel<<<nblk, 256, NODE_SMEM_BYTES>>>(                        // 7
        h0, aggp, W_up1, b_up1, W_up2, b_up2, h1, N);

    float* hc = h1;
    float* hn = h0;
    for (int l = 1; l < L; l++) {
        const float* W1l = W_msg1 + (size_t)l * DIN * DH;
        prep_gemm_kernel<<<prep_grid, 256, PREP_SMEM_BYTES>>>(
            hc, W1l, b_msg1 + (size_t)l * DH, pdp, psp, aggp, N);
        edge_kernel<<<(E + 255) / 256, 256, EDGE_SMEM_BYTES>>>(
            pdp, psp, W1l + (size_t)256 * DH,
            W_msg2 + (size_t)l * DH * FM_DIM, b_msg2 + (size_t)l * FM_DIM,
            esp, edp, en2p, aggp, E);
        node_update_kernel<<<nblk, 256, NODE_SMEM_BYTES>>>(
            hc, aggp,
            W_up1 + (size_t)l * UIN * UH, b_up1 + (size_t)l * UH,
            W_up2 + (size_t)l * UH * F_DIM, b_up2 + (size_t)l * F_DIM,
            hn, N);
        float* t = hc; hc = hn; hn = t;
    }

    zero_kernel<<<(G * HID + 255) / 256, 256>>>(pooledp, G * HID);
    proj_pool_kernel<<<nblk, 256, PROJ_SMEM_BYTES>>>(
        hc, batch, Wp1, bp1, Wp2, bp2, pooledp, N);
    readout_kernel<<<(G + 63) / 64, 256, RO_SMEM_BYTES>>>(
        pooledp, Wr1, br1, Wr2, br2, out, G);
}

// round 14
// speedup vs baseline: 1.1706x; 1.1706x over previous
#include <cuda_runtime.h>
#include <cuda_fp16.h>
#include <cstdint>

#define F_DIM   128
#define FM_DIM  16
#define DIN     257
#define DH      514
#define UIN     144
#define UH      256
#define HID     128
#define T_OUT   12
#define SP      520     // padded row stride for Pd/Ps in HALVES (1040B, 16B-aligned)

#define MAXN 50048
#define MAXE 800000
#define MAXG 1024

// ---------------- scratch (no allocations allowed) ----------------
__device__ __align__(256) float  g_h0[MAXN * F_DIM];
__device__ __align__(256) float  g_h1[MAXN * F_DIM];
__device__ __align__(256) float  g_en2[MAXE];      // norm2, dst-sorted order
__device__ __align__(256) float  g_en2r[MAXE];     // norm2, raw edge order
__device__ __align__(256) float  g_agg[MAXN * FM_DIM];
__device__ __align__(256) float  g_pooled[MAXG * HID];
__device__ __align__(256) __half g_Pd[MAXN * SP];  // h @ W1[0:128] + b1   (fp16)
__device__ __align__(256) __half g_Ps[MAXN * SP];  // h @ W1[128:256]      (fp16)
__device__ __align__(256) int    g_cur[MAXN];      // scan cursor
__device__ __align__(256) int    g_es[MAXE];       // sorted src
__device__ __align__(256) int    g_ed[MAXE];       // sorted dst

// ---------------- helpers ----------------
__device__ __forceinline__ float swishf(float x) {
    return __fdividef(x, 1.0f + __expf(-x));
}

typedef unsigned long long ull;

__device__ __forceinline__ void fma2(ull& d, ull a, ull b) {
    asm("fma.rn.f32x2 %0, %1, %2, %0;" : "+l"(d) : "l"(a), "l"(b));
}
__device__ __forceinline__ ull pack2(float x) {
    ull r;
    asm("mov.b64 %0, {%1, %1};" : "=l"(r) : "f"(x));
    return r;
}
__device__ __forceinline__ void unpack2(ull v, float& lo, float& hi) {
    asm("mov.b64 {%0, %1}, %2;" : "=f"(lo), "=f"(hi) : "l"(v));
}

// ---------------- small kernels ----------------
__global__ void zero_kernel(float* p, int n) {
    int i = blockIdx.x * blockDim.x + threadIdx.x;
    if (i < n) p[i] = 0.0f;
}

// h init (+ zero the sort cursor, fused to save a launch)
__global__ void init_h_kernel(const void* zptr, const float* __restrict__ emb,
                              float* __restrict__ h, int* __restrict__ cur, int N) {
    int i = blockIdx.x * blockDim.x + threadIdx.x;
    if (i < N) cur[i] = 0;
    if (i >= N * F_DIM) return;
    int node = i / F_DIM, f = i % F_DIM;
    const int* z32 = (const int*)zptr;
    bool is64 = (z32[1] == 0) && (z32[3] == 0) && (z32[5] == 0);
    long long zv = is64 ? ((const long long*)zptr)[node] : (long long)z32[node];
    int e = (zv == 1) ? 0 : (int)(zv - 5);
    h[i] = emb[e * F_DIM + f];
}

__global__ void norm2_kernel(const float* __restrict__ pos,
                             const int* __restrict__ ei,
                             float* __restrict__ norm2, int E) {
    int e = blockIdx.x * blockDim.x + threadIdx.x;
    if (e >= E) return;
    int s = ei[e], d = ei[E + e];
    float dx = pos[s * 3 + 0] - pos[d * 3 + 0];
    float dy = pos[s * 3 + 1] - pos[d * 3 + 1];
    float dz = pos[s * 3 + 2] - pos[d * 3 + 2];
    norm2[e] = dx * dx + dy * dy + dz * dz;
}

// ---------------- counting sort of edges by dst ----------------
__global__ void hist_kernel(const int* __restrict__ ei, int* __restrict__ cnt, int E) {
    int e = blockIdx.x * blockDim.x + threadIdx.x;
    if (e < E) atomicAdd(&cnt[ei[E + e]], 1);
}

__global__ void scan_kernel(int* __restrict__ cnt, int* __restrict__ cur, int N) {
    __shared__ int sdata[1024];
    __shared__ int carry_s;
    if (threadIdx.x == 0) carry_s = 0;
    __syncthreads();
    for (int base = 0; base < N; base += 1024) {
        int i = base + threadIdx.x;
        int v = (i < N) ? cnt[i] : 0;
        sdata[threadIdx.x] = v;
        __syncthreads();
        for (int ofs = 1; ofs < 1024; ofs <<= 1) {
            int t = (threadIdx.x >= ofs) ? sdata[threadIdx.x - ofs] : 0;
            __syncthreads();
            sdata[threadIdx.x] += t;
            __syncthreads();
        }
        int excl = sdata[threadIdx.x] - v + carry_s;
        if (i < N) cur[i] = excl;
        __syncthreads();
        if (threadIdx.x == 0) carry_s += sdata[1023];
        __syncthreads();
    }
}

__global__ void scatter_kernel(const int* __restrict__ ei,
                               const float* __restrict__ en2r,
                               int* __restrict__ cur,
                               int* __restrict__ es, int* __restrict__ ed,
                               float* __restrict__ en2, int E) {
    int e = blockIdx.x * blockDim.x + threadIdx.x;
    if (e >= E) return;
    int s = ei[e], d = ei[E + e];
    int p = atomicAdd(&cur[d], 1);
    es[p] = s; ed[p] = d;
    en2[p] = en2r[e];
}

// ---------------- per-node pre-GEMM: P = h @ W (+bias), fp16 out ----------
// 128-node x 128-col tile, 8x8 output per thread (f32x2), 2 CTA/SM.
// Slice (y=0,z=0) also zeroes agg (fused; kernel boundary orders it vs edge).
#define PREP_SMEM_BYTES ((128 * 132 + 8 * 132) * 4)

__global__ __launch_bounds__(256)
void prep_gemm_kernel(const float* __restrict__ h, const float* __restrict__ W1,
                      const float* __restrict__ bias,
                      __half* __restrict__ Pd, __half* __restrict__ Ps,
                      float* __restrict__ agg, int N) {
    extern __shared__ float sm[];
    float* sH = sm;              // 128 x 132
    float* sB = sH + 128 * 132;  // 8 x 132

    const int tid = threadIdx.x;
    const int n0 = blockIdx.x * 128;
    const int c0 = blockIdx.y * 128;
    const int which = blockIdx.z;
    const float* W = W1 + (size_t)which * 128 * DH;
    __half* P = which ? Ps : Pd;

    if (blockIdx.y == 0 && blockIdx.z == 0) {
        for (int i = blockIdx.x * 256 + tid; i < N * FM_DIM; i += gridDim.x * 256)
            agg[i] = 0.0f;
    }

    // load h tile [128 x 128] as float4
    for (int idx = tid; idx < 128 * 32; idx += 256) {
        int r = idx >> 5, c4 = (idx & 31) * 4;
        int node = n0 + r;
        float4 v = make_float4(0.f, 0.f, 0.f, 0.f);
        if (node < N) v = *(const float4*)(h + (size_t)node * F_DIM + c4);
        *(float4*)(sH + r * 132 + c4) = v;
    }
    __syncthreads();

    const int ty = tid >> 4, tx = tid & 15;
    const int r0 = ty * 8, ct = tx * 8;

    ull C[8][4];
    #pragma unroll
    for (int i = 0; i < 8; i++)
        #pragma unroll
        for (int j = 0; j < 4; j++) C[i][j] = 0;

    for (int k0 = 0; k0 < 128; k0 += 8) {
        #pragma unroll
        for (int it = 0; it < 4; it++) {
            int t = tid + it * 256;
            int kk = t >> 7, c = t & 127;
            int col = c0 + c;
            sB[kk * 132 + c] = (col < DH) ? W[(size_t)(k0 + kk) * DH + col] : 0.0f;
        }
        __syncthreads();
        #pragma unroll
        for (int kk = 0; kk < 8; kk++) {
            const float* bp = sB + kk * 132 + ct;
            ull b0 = *(const ull*)(bp);
            ull b1 = *(const ull*)(bp + 2);
            ull b2v = *(const ull*)(bp + 4);
            ull b3 = *(const ull*)(bp + 6);
            #pragma unroll
            for (int i = 0; i < 8; i++) {
                ull aa = pack2(sH[(r0 + i) * 132 + k0 + kk]);
                fma2(C[i][0], aa, b0); fma2(C[i][1], aa, b1);
                fma2(C[i][2], aa, b2v); fma2(C[i][3], aa, b3);
            }
        }
        __syncthreads();
    }

    #pragma unroll
    for (int i = 0; i < 8; i++) {
        int node = n0 + r0 + i;
        if (node >= N) continue;
        float v[8];
        unpack2(C[i][0], v[0], v[1]); unpack2(C[i][1], v[2], v[3]);
        unpack2(C[i][2], v[4], v[5]); unpack2(C[i][3], v[6], v[7]);
        int col0 = c0 + ct;
        __half* prow = P + (size_t)node * SP + col0;
        #pragma unroll
        for (int j = 0; j < 8; j++)
            v[j] += (which == 0 && col0 + j < DH) ? bias[col0 + j] : 0.0f;
        if (col0 + 8 <= DH) {
            __half2 h01 = __floats2half2_rn(v[0], v[1]);
            __half2 h23 = __floats2half2_rn(v[2], v[3]);
            __half2 h45 = __floats2half2_rn(v[4], v[5]);
            __half2 h67 = __floats2half2_rn(v[6], v[7]);
            uint4 st;
            st.x = *(unsigned*)&h01; st.y = *(unsigned*)&h23;
            st.z = *(unsigned*)&h45; st.w = *(unsigned*)&h67;
            *(uint4*)prow = st;
        } else {
            #pragma unroll
            for (int j = 0; j < 8; j++)
                if (col0 + j < SP)
                    prow[j] = __float2half_rn((col0 + j < DH) ? v[j] : 0.0f);
        }
    }
}

// ---------------- edge phase: 2 edges/thread, register-resident ----------
// W2-row broadcast LDS amortized over 2 edges; sorted edges mean the pair
// usually shares dst (merged Pd lines + merged epilogue atomics).
#define EDGE_SMEM_BYTES ((516 * 16 + 516) * 4)

__global__ __launch_bounds__(256)
void edge_kernel(const __half* __restrict__ Pd, const __half* __restrict__ Ps,
                 const float* __restrict__ Wn,   // W1 row 256 (norm2 row)
                 const float* __restrict__ W2, const float* __restrict__ b2,
                 const int* __restrict__ es, const int* __restrict__ ed,
                 const float* __restrict__ en2,
                 float* __restrict__ agg, int E) {
    extern __shared__ float sm[];
    float* sW2 = sm;               // 516 x 16 (rows >=514 zero)
    float* sWn = sW2 + 516 * 16;   // 516 (pad zero)

    const int tid = threadIdx.x;
    for (int i = tid; i < 516 * 16; i += 256) {
        int k = i >> 4;
        sW2[i] = (k < DH) ? W2[i] : 0.0f;
    }
    for (int i = tid; i < 516; i += 256)
        sWn[i] = (i < DH) ? Wn[i] : 0.0f;
    __syncthreads();

    const int e0 = (blockIdx.x * 256 + tid) * 2;
    const bool a0 = (e0 < E), a1 = (e0 + 1 < E);
    int d0 = 0, s0 = 0, d1 = 0, s1 = 0;
    float n20 = 0.0f, n21 = 0.0f;
    if (a0) { d0 = ed[e0]; s0 = es[e0]; n20 = en2[e0]; }
    if (a1) { d1 = ed[e0 + 1]; s1 = es[e0 + 1]; n21 = en2[e0 + 1]; }
    const __half* pd0 = Pd + (size_t)d0 * SP;
    const __half* ps0 = Ps + (size_t)s0 * SP;
    const __half* pd1 = Pd + (size_t)d1 * SP;
    const __half* ps1 = Ps + (size_t)s1 * SP;

    ull m0[8], m1[8];
    #pragma unroll
    for (int j = 0; j < 8; j++) { m0[j] = 0; m1[j] = 0; }

    // buffers: 2 slots of 8 halves per edge per array (chunk = 16 k)
    uint4 bd0[2], bs0[2], bd1[2], bs1[2];
    #pragma unroll
    for (int j = 0; j < 2; j++) {
        bd0[j] = *(const uint4*)(pd0 + j * 8);
        bs0[j] = *(const uint4*)(ps0 + j * 8);
        bd1[j] = *(const uint4*)(pd1 + j * 8);
        bs1[j] = *(const uint4*)(ps1 + j * 8);
    }

    for (int c = 0; c < 32; c++) {
        const int k0 = c * 16;
        #pragma unroll
        for (int j = 0; j < 2; j++) {
            const __half2* hd0 = (const __half2*)&bd0[j];
            const __half2* hs0 = (const __half2*)&bs0[j];
            const __half2* hd1 = (const __half2*)&bd1[j];
            const __half2* hs1 = (const __half2*)&bs1[j];
            float2 f00 = __half22float2(__hadd2(hd0[0], hs0[0]));
            float2 f01 = __half22float2(__hadd2(hd0[1], hs0[1]));
            float2 f02 = __half22float2(__hadd2(hd0[2], hs0[2]));
            float2 f03 = __half22float2(__hadd2(hd0[3], hs0[3]));
            float2 f10 = __half22float2(__hadd2(hd1[0], hs1[0]));
            float2 f11 = __half22float2(__hadd2(hd1[1], hs1[1]));
            float2 f12 = __half22float2(__hadd2(hd1[2], hs1[2]));
            float2 f13 = __half22float2(__hadd2(hd1[3], hs1[3]));
            // refill this slot for the next chunk (covered by GEMM below)
            if (c < 31) {
                int off = k0 + 16 + j * 8;
                bd0[j] = *(const uint4*)(pd0 + off);
                bs0[j] = *(const uint4*)(ps0 + off);
                bd1[j] = *(const uint4*)(pd1 + off);
                bs1[j] = *(const uint4*)(ps1 + off);
            }
            const int kb = k0 + j * 8;
            float4 wl = *(const float4*)(sWn + kb);
            float4 wh = *(const float4*)(sWn + kb + 4);
            float x0[8], x1[8];
            x0[0] = fmaf(n20, wl.x, f00.x); x0[1] = fmaf(n20, wl.y, f00.y);
            x0[2] = fmaf(n20, wl.z, f01.x); x0[3] = fmaf(n20, wl.w, f01.y);
            x0[4] = fmaf(n20, wh.x, f02.x); x0[5] = fmaf(n20, wh.y, f02.y);
            x0[6] = fmaf(n20, wh.z, f03.x); x0[7] = fmaf(n20, wh.w, f03.y);
            x1[0] = fmaf(n21, wl.x, f10.x); x1[1] = fmaf(n21, wl.y, f10.y);
            x1[2] = fmaf(n21, wl.z, f11.x); x1[3] = fmaf(n21, wl.w, f11.y);
            x1[4] = fmaf(n21, wh.x, f12.x); x1[5] = fmaf(n21, wh.y, f12.y);
            x1[6] = fmaf(n21, wh.z, f13.x); x1[7] = fmaf(n21, wh.w, f13.y);
            #pragma unroll
            for (int q = 0; q < 8; q++) {
                ull a0p = pack2(swishf(x0[q]));
                ull a1p = pack2(swishf(x1[q]));
                const float* wp = sW2 + (kb + q) * 16;
                float4 w0 = *(const float4*)(wp);
                float4 w1 = *(const float4*)(wp + 4);
                float4 w2v = *(const float4*)(wp + 8);
                float4 w3 = *(const float4*)(wp + 12);
                ull u0 = *(ull*)&w0, u1 = *((ull*)&w0 + 1);
                ull u2 = *(ull*)&w1, u3 = *((ull*)&w1 + 1);
                ull u4 = *(ull*)&w2v, u5 = *((ull*)&w2v + 1);
                ull u6 = *(ull*)&w3, u7 = *((ull*)&w3 + 1);
                fma2(m0[0], a0p, u0); fma2(m0[1], a0p, u1);
                fma2(m0[2], a0p, u2); fma2(m0[3], a0p, u3);
                fma2(m0[4], a0p, u4); fma2(m0[5], a0p, u5);
                fma2(m0[6], a0p, u6); fma2(m0[7], a0p, u7);
                fma2(m1[0], a1p, u0); fma2(m1[1], a1p, u1);
                fma2(m1[2], a1p, u2); fma2(m1[3], a1p, u3);
                fma2(m1[4], a1p, u4); fma2(m1[5], a1p, u5);
                fma2(m1[6], a1p, u6); fma2(m1[7], a1p, u7);
            }
        }
    }

    // tail k = 512..513
    {
        float2 t0 = __half22float2(__hadd2(*(__half2*)(pd0 + 512), *(__half2*)(ps0 + 512)));
        float2 t1 = __half22float2(__hadd2(*(__half2*)(pd1 + 512), *(__half2*)(ps1 + 512)));
        float w512 = sWn[512], w513 = sWn[513];
        float xe0[2] = { fmaf(n20, w512, t0.x), fmaf(n20, w513, t0.y) };
        float xe1[2] = { fmaf(n21, w512, t1.x), fmaf(n21, w513, t1.y) };
        #pragma unroll
        for (int q = 0; q < 2; q++) {
            ull a0p = pack2(swishf(xe0[q]));
            ull a1p = pack2(swishf(xe1[q]));
            const float* wp = sW2 + (512 + q) * 16;
            float4 w0 = *(const float4*)(wp);
            float4 w1 = *(const float4*)(wp + 4);
            float4 w2v = *(const float4*)(wp + 8);
            float4 w3 = *(const float4*)(wp + 12);
            ull u0 = *(ull*)&w0, u1 = *((ull*)&w0 + 1);
            ull u2 = *(ull*)&w1, u3 = *((ull*)&w1 + 1);
            ull u4 = *(ull*)&w2v, u5 = *((ull*)&w2v + 1);
            ull u6 = *(ull*)&w3, u7 = *((ull*)&w3 + 1);
            fma2(m0[0], a0p, u0); fma2(m0[1], a0p, u1);
            fma2(m0[2], a0p, u2); fma2(m0[3], a0p, u3);
            fma2(m0[4], a0p, u4); fma2(m0[5], a0p, u5);
            fma2(m0[6], a0p, u6); fma2(m0[7], a0p, u7);
            fma2(m1[0], a1p, u0); fma2(m1[1], a1p, u1);
            fma2(m1[2], a1p, u2); fma2(m1[3], a1p, u3);
            fma2(m1[4], a1p, u4); fma2(m1[5], a1p, u5);
            fma2(m1[6], a1p, u6); fma2(m1[7], a1p, u7);
        }
    }

    // epilogue: swish(m2 + b2) -> atomic scatter (merge when pair shares dst)
    if (a0 && a1 && d0 == d1) {
        float* ap = agg + (size_t)d0 * FM_DIM;
        #pragma unroll
        for (int j = 0; j < 8; j++) {
            float lo0, hi0, lo1, hi1;
            unpack2(m0[j], lo0, hi0);
            unpack2(m1[j], lo1, hi1);
            float b0v = b2[2 * j], b1v = b2[2 * j + 1];
            atomicAdd(ap + 2 * j,     swishf(lo0 + b0v) + swishf(lo1 + b0v));
            atomicAdd(ap + 2 * j + 1, swishf(hi0 + b1v) + swishf(hi1 + b1v));
        }
    } else {
        if (a0) {
            float* ap = agg + (size_t)d0 * FM_DIM;
            #pragma unroll
            for (int j = 0; j < 8; j++) {
                float lo, hi;
                unpack2(m0[j], lo, hi);
                atomicAdd(ap + 2 * j,     swishf(lo + b2[2 * j]));
                atomicAdd(ap + 2 * j + 1, swishf(hi + b2[2 * j + 1]));
            }
        }
        if (a1) {
            float* ap = agg + (size_t)d1 * FM_DIM;
            #pragma unroll
            for (int j = 0; j < 8; j++) {
                float lo, hi;
                unpack2(m1[j], lo, hi);
                atomicAdd(ap + 2 * j,     swishf(lo + b2[2 * j]));
                atomicAdd(ap + 2 * j + 1, swishf(hi + b2[2 * j + 1]));
            }
        }
    }
}

// ---------------- fused node update ----------------
#define SU_STR 148
#define NODE_SMEM_BYTES ((64 * SU_STR + 64 * 132 + 8 * 132) * 4)

__global__ __launch_bounds__(256)
void node_update_kernel(const float* __restrict__ h,
                        const float* __restrict__ agg,
                        const float* __restrict__ W1, const float* __restrict__ b1,
                        const float* __restrict__ W2, const float* __restrict__ b2,
                        float* __restrict__ hout, int N) {
    extern __shared__ float sm[];
    float* sU  = sm;
    float* sU1 = sU + 64 * SU_STR;
    float* sB  = sU1 + 64 * 132;

    const int tid = threadIdx.x;
    const int n0 = blockIdx.x * 64;

    for (int idx = tid; idx < 64 * UIN; idx += 256) {
        int r = idx / UIN, c = idx % UIN;
        int node = n0 + r;
        float v = 0.0f;
        if (node < N)
            v = (c < FM_DIM) ? agg[(size_t)node * FM_DIM + c]
                             : h[(size_t)node * F_DIM + (c - FM_DIM)];
        sU[r * SU_STR + c] = v;
    }
    __syncthreads();

    const int ty = tid >> 4, tx = tid & 15;
    const int r0 = ty * 4, ct = tx * 8;

    float C2[4][8];
    #pragma unroll
    for (int i = 0; i < 4; i++)
        #pragma unroll
        for (int j = 0; j < 8; j++) C2[i][j] = 0.0f;

    for (int c0 = 0; c0 < UH; c0 += 128) {
        float C1[4][8];
        #pragma unroll
        for (int i = 0; i < 4; i++)
            #pragma unroll
            for (int j = 0; j < 8; j++) C1[i][j] = 0.0f;

        for (int k0 = 0; k0 < UIN; k0 += 8) {
            #pragma unroll
            for (int it = 0; it < 4; it++) {
                int t = tid + it * 256;
                int kk = t >> 7, c = t & 127;
                sB[kk * 132 + c] = W1[(size_t)(k0 + kk) * UH + c0 + c];
            }
            __syncthreads();
            #pragma unroll
            for (int kk = 0; kk < 8; kk++) {
                float4 b0 = *(const float4*)(sB + kk * 132 + ct);
                float4 b1v = *(const float4*)(sB + kk * 132 + ct + 4);
                #pragma unroll
                for (int i = 0; i < 4; i++) {
                    float a = sU[(r0 + i) * SU_STR + k0 + kk];
                    C1[i][0] += a * b0.x; C1[i][1] += a * b0.y;
                    C1[i][2] += a * b0.z; C1[i][3] += a * b0.w;
                    C1[i][4] += a * b1v.x; C1[i][5] += a * b1v.y;
                    C1[i][6] += a * b1v.z; C1[i][7] += a * b1v.w;
                }
            }
            __syncthreads();
        }
        #pragma unroll
        for (int i = 0; i < 4; i++)
            #pragma unroll
            for (int j = 0; j < 8; j++)
                sU1[(r0 + i) * 132 + ct + j] = swishf(C1[i][j] + b1[c0 + ct + j]);
        __syncthreads();

        for (int k0 = 0; k0 < 128; k0 += 8) {
            #pragma unroll
            for (int it = 0; it < 4; it++) {
                int t = tid + it * 256;
                int kk = t >> 7, c = t & 127;
                sB[kk * 132 + c] = W2[(size_t)(c0 + k0 + kk) * F_DIM + c];
            }
            __syncthreads();
            #pragma unroll
            for (int kk = 0; kk < 8; kk++) {
                float4 b0 = *(const float4*)(sB + kk * 132 + ct);
                float4 b1v = *(const float4*)(sB + kk * 132 + ct + 4);
                #pragma unroll
                for (int i = 0; i < 4; i++) {
                    float a = sU1[(r0 + i) * 132 + k0 + kk];
                    C2[i][0] += a * b0.x; C2[i][1] += a * b0.y;
                    C2[i][2] += a * b0.z; C2[i][3] += a * b0.w;
                    C2[i][4] += a * b1v.x; C2[i][5] += a * b1v.y;
                    C2[i][6] += a * b1v.z; C2[i][7] += a * b1v.w;
                }
            }
            __syncthreads();
        }
    }

    #pragma unroll
    for (int i = 0; i < 4; i++) {
        int node = n0 + r0 + i;
        if (node < N) {
            #pragma unroll
            for (int j = 0; j < 8; j++)
                hout[(size_t)node * F_DIM + ct + j] =
                    C2[i][j] + b2[ct + j] + sU[(r0 + i) * SU_STR + FM_DIM + ct + j];
        }
    }
}

// ---------------- projection + sorted-batch pooling ----------------
#define PROJ_SMEM_BYTES ((64 * 132 * 2 + 8 * 132) * 4 + 64 * 4)

__global__ __launch_bounds__(256)
void proj_pool_kernel(const float* __restrict__ h,
                      const int* __restrict__ batch,
                      const float* __restrict__ Wp1, const float* __restrict__ bp1,
                      const float* __restrict__ Wp2, const float* __restrict__ bp2,
                      float* __restrict__ pooled, int N) {
    extern __shared__ float sm[];
    float* sH = sm;
    float* sG = sH + 64 * 132;
    float* sB = sG + 64 * 132;
    int* sBatch = (int*)(sB + 8 * 132);

    const int tid = threadIdx.x;
    const int n0 = blockIdx.x * 64;

    for (int idx = tid; idx < 64 * HID; idx += 256) {
        int r = idx >> 7, c = idx & 127;
        int node = n0 + r;
        sH[r * 132 + c] = (node < N) ? h[(size_t)node * F_DIM + c] : 0.0f;
    }
    if (tid < 64) {
        int node = n0 + tid;
        sBatch[tid] = (node < N) ? batch[node] : -1;
    }
    __syncthreads();

    const int ty = tid >> 4, tx = tid & 15;
    const int r0 = ty * 4, ct = tx * 8;

    float C1[4][8];
    #pragma unroll
    for (int i = 0; i < 4; i++)
        #pragma unroll
        for (int j = 0; j < 8; j++) C1[i][j] = 0.0f;

    for (int k0 = 0; k0 < HID; k0 += 8) {
        #pragma unroll
        for (int it = 0; it < 4; it++) {
            int t = tid + it * 256;
            int kk = t >> 7, c = t & 127;
            sB[kk * 132 + c] = Wp1[(size_t)(k0 + kk) * HID + c];
        }
        __syncthreads();
        #pragma unroll
        for (int kk = 0; kk < 8; kk++) {
            float4 b0 = *(const float4*)(sB + kk * 132 + ct);
            float4 b1v = *(const float4*)(sB + kk * 132 + ct + 4);
            #pragma unroll
            for (int i = 0; i < 4; i++) {
                float a = sH[(r0 + i) * 132 + k0 + kk];
                C1[i][0] += a * b0.x; C1[i][1] += a * b0.y;
                C1[i][2] += a * b0.z; C1[i][3] += a * b0.w;
                C1[i][4] += a * b1v.x; C1[i][5] += a * b1v.y;
                C1[i][6] += a * b1v.z; C1[i][7] += a * b1v.w;
            }
        }
        __syncthreads();
    }
    #pragma unroll
    for (int i = 0; i < 4; i++)
        #pragma unroll
        for (int j = 0; j < 8; j++)
            sG[(r0 + i) * 132 + ct + j] = swishf(C1[i][j] + bp1[ct + j]);
    __syncthreads();

    float C2[4][8];
    #pragma unroll
    for (int i = 0; i < 4; i++)
        #pragma unroll
        for (int j = 0; j < 8; j++) C2[i][j] = 0.0f;

    for (int k0 = 0; k0 < HID; k0 += 8) {
        #pragma unroll
        for (int it = 0; it < 4; it++) {
            int t = tid + it * 256;
            int kk = t >> 7, c = t & 127;
            sB[kk * 132 + c] = Wp2[(size_t)(k0 + kk) * HID + c];
        }
        __syncthreads();
        #pragma unroll
        for (int kk = 0; kk < 8; kk++) {
            float4 b0 = *(const float4*)(sB + kk * 132 + ct);
            float4 b1v = *(const float4*)(sB + kk * 132 + ct + 4);
            #pragma unroll
            for (int i = 0; i < 4; i++) {
                float a = sG[(r0 + i) * 132 + k0 + kk];
                C2[i][0] += a * b0.x; C2[i][1] += a * b0.y;
                C2[i][2] += a * b0.z; C2[i][3] += a * b0.w;
                C2[i][4] += a * b1v.x; C2[i][5] += a * b1v.y;
                C2[i][6] += a * b1v.z; C2[i][7] += a * b1v.w;
            }
        }
        __syncthreads();
    }
    #pragma unroll
    for (int i = 0; i < 4; i++)
        #pragma unroll
        for (int j = 0; j < 8; j++)
            sH[(r0 + i) * 132 + ct + j] = C2[i][j] + bp2[ct + j];
    __syncthreads();

    if (tid < HID) {
        int col = tid;
        int g = sBatch[0];
        float acc = 0.0f;
        for (int r = 0; r < 64; r++) {
            int gg = sBatch[r];
            if (gg != g) {
                if (g >= 0) atomicAdd(&pooled[(size_t)g * HID + col], acc);
                acc = 0.0f;
                g = gg;
            }
            acc += sH[r * 132 + col];
        }
        if (g >= 0) atomicAdd(&pooled[(size_t)g * HID + col], acc);
    }
}

// ---------------- readout ----------------
#define RO_SMEM_BYTES ((64 * 132 * 2 + 8 * 132) * 4)

__global__ __launch_bounds__(256)
void readout_kernel(const float* __restrict__ pooled,
                    const float* __restrict__ Wr1, const float* __restrict__ br1,
                    const float* __restrict__ Wr2, const float* __restrict__ br2,
                    float* __restrict__ out, int G) {
    extern __shared__ float sm[];
    float* sP = sm;
    float* sR = sP + 64 * 132;
    float* sB = sR + 64 * 132;

    const int tid = threadIdx.x;
    const int g0 = blockIdx.x * 64;

    for (int idx = tid; idx < 64 * HID; idx += 256) {
        int r = idx >> 7, c = idx & 127;
        int g = g0 + r;
        sP[r * 132 + c] = (g < G) ? pooled[(size_t)g * HID + c] : 0.0f;
    }
    __syncthreads();

    const int ty = tid >> 4, tx = tid & 15;
    const int r0 = ty * 4, ct = tx * 8;

    float C1[4][8];
    #pragma unroll
    for (int i = 0; i < 4; i++)
        #pragma unroll
        for (int j = 0; j < 8; j++) C1[i][j] = 0.0f;

    for (int k0 = 0; k0 < HID; k0 += 8) {
        #pragma unroll
        for (int it = 0; it < 4; it++) {
            int t = tid + it * 256;
            int kk = t >> 7, c = t & 127;
            sB[kk * 132 + c] = Wr1[(size_t)(k0 + kk) * HID + c];
        }
        __syncthreads();
        #pragma unroll
        for (int kk = 0; kk < 8; kk++) {
            float4 b0 = *(const float4*)(sB + kk * 132 + ct);
            float4 b1v = *(const float4*)(sB + kk * 132 + ct + 4);
            #pragma unroll
            for (int i = 0; i < 4; i++) {
                float a = sP[(r0 + i) * 132 + k0 + kk];
                C1[i][0] += a * b0.x; C1[i][1] += a * b0.y;
                C1[i][2] += a * b0.z; C1[i][3] += a * b0.w;
                C1[i][4] += a * b1v.x; C1[i][5] += a * b1v.y;
                C1[i][6] += a * b1v.z; C1[i][7] += a * b1v.w;
            }
        }
        __syncthreads();
    }
    #pragma unroll
    for (int i = 0; i < 4; i++)
        #pragma unroll
        for (int j = 0; j < 8; j++)
            sR[(r0 + i) * 132 + ct + j] = swishf(C1[i][j] + br1[ct + j]);
    __syncthreads();

    for (int idx = tid; idx < 64 * T_OUT; idx += 256) {
        int e = idx / T_OUT, t = idx % T_OUT;
        int g = g0 + e;
        if (g < G) {
            float acc = br2[t];
            #pragma unroll 4
            for (int k = 0; k < HID; k++)
                acc += sR[e * 132 + k] * Wr2[(size_t)k * T_OUT + t];
            out[(size_t)g * T_OUT + t] = acc;
        }
    }
}

// ---------------- launch ----------------
extern "C" void kernel_launch(void* const* d_in, const int* in_sizes, int n_in,
                              void* d_out, int out_size) {
    const float* pos    = (const float*)d_in[0];
    const void*  zptr   = d_in[1];
    const int*   ei     = (const int*)d_in[2];
    const int*   batch  = (const int*)d_in[3];
    const float* emb    = (const float*)d_in[4];
    const float* W_msg1 = (const float*)d_in[5];
    const float* b_msg1 = (const float*)d_in[6];
    const float* W_msg2 = (const float*)d_in[7];
    const float* b_msg2 = (const float*)d_in[8];
    const float* W_up1  = (const float*)d_in[9];
    const float* b_up1  = (const float*)d_in[10];
    const float* W_up2  = (const float*)d_in[11];
    const float* b_up2  = (const float*)d_in[12];
    const float* Wp1    = (const float*)d_in[13];
    const float* bp1    = (const float*)d_in[14];
    const float* Wp2    = (const float*)d_in[15];
    const float* bp2    = (const float*)d_in[16];
    const float* Wr1    = (const float*)d_in[17];
    const float* br1    = (const float*)d_in[18];
    const float* Wr2    = (const float*)d_in[19];
    const float* br2    = (const float*)d_in[20];
    float* out = (float*)d_out;

    const int N = in_sizes[0] / 3;
    const int E = in_sizes[2] / 2;
    const int L = in_sizes[5] / (DIN * DH);
    const int G = out_size / T_OUT;

    float *h0, *h1, *aggp, *pooledp, *en2p, *en2rp;
    __half *pdp, *psp;
    int *curp, *esp, *edp;
    cudaGetSymbolAddress((void**)&h0, g_h0);
    cudaGetSymbolAddress((void**)&h1, g_h1);
    cudaGetSymbolAddress((void**)&aggp, g_agg);
    cudaGetSymbolAddress((void**)&pooledp, g_pooled);
    cudaGetSymbolAddress((void**)&en2p, g_en2);
    cudaGetSymbolAddress((void**)&en2rp, g_en2r);
    cudaGetSymbolAddress((void**)&pdp, g_Pd);
    cudaGetSymbolAddress((void**)&psp, g_Ps);
    cudaGetSymbolAddress((void**)&curp, g_cur);
    cudaGetSymbolAddress((void**)&esp, g_es);
    cudaGetSymbolAddress((void**)&edp, g_ed);

    cudaFuncSetAttribute(edge_kernel,
                         cudaFuncAttributeMaxDynamicSharedMemorySize, EDGE_SMEM_BYTES);
    cudaFuncSetAttribute(prep_gemm_kernel,
                         cudaFuncAttributeMaxDynamicSharedMemorySize, PREP_SMEM_BYTES);
    cudaFuncSetAttribute(node_update_kernel,
                         cudaFuncAttributeMaxDynamicSharedMemorySize, NODE_SMEM_BYTES);
    cudaFuncSetAttribute(proj_pool_kernel,
                         cudaFuncAttributeMaxDynamicSharedMemorySize, PROJ_SMEM_BYTES);
    cudaFuncSetAttribute(readout_kernel,
                         cudaFuncAttributeMaxDynamicSharedMemorySize, RO_SMEM_BYTES);

    const int nblk = (N + 63) / 64;
    const dim3 prep_grid((N + 127) / 128, 5, 2);
    const int eblk = (E + 511) / 512;   // 2 edges per thread

    // ---- launch order puts prep_gemm at local index 3 (ncu -s 5 -c 1) ----
    init_h_kernel<<<(N * F_DIM + 255) / 256, 256>>>(zptr, emb, h0, curp, N);   // 0
    hist_kernel<<<(E + 255) / 256, 256>>>(ei, curp, E);                        // 1
    scan_kernel<<<1, 1024>>>(curp, curp, N);                                   // 2
    prep_gemm_kernel<<<prep_grid, 256, PREP_SMEM_BYTES>>>(                     // 3 <- profiled
        h0, W_msg1, b_msg1, pdp, psp, aggp, N);
    norm2_kernel<<<(E + 255) / 256, 256>>>(pos, ei, en2rp, E);                 // 4
    scatter_kernel<<<(E + 255) / 256, 256>>>(ei, en2rp, curp, esp, edp, en2p, E); // 5
    edge_kernel<<<eblk, 256, EDGE_SMEM_BYTES>>>(                               // 6
        pdp, psp, W_msg1 + (size_t)256 * DH, W_msg2, b_msg2,
        esp, edp, en2p, aggp, E);
    node_update_kernel<<<nblk, 256, NODE_SMEM_BYTES>>>(                        // 7
        h0, aggp, W_up1, b_up1, W_up2, b_up2, h1, N);

    float* hc = h1;
    float* hn = h0;
    for (int l = 1; l < L; l++) {
        const float* W1l = W_msg1 + (size_t)l * DIN * DH;
        prep_gemm_kernel<<<prep_grid, 256, PREP_SMEM_BYTES>>>(
            hc, W1l, b_msg1 + (size_t)l * DH, pdp, psp, aggp, N);
        edge_kernel<<<eblk, 256, EDGE_SMEM_BYTES>>>(
            pdp, psp, W1l + (size_t)256 * DH,
            W_msg2 + (size_t)l * DH * FM_DIM, b_msg2 + (size_t)l * FM_DIM,
            esp, edp, en2p, aggp, E);
        node_update_kernel<<<nblk, 256, NODE_SMEM_BYTES>>>(
            hc, aggp,
            W_up1 + (size_t)l * UIN * UH, b_up1 + (size_t)l * UH,
            W_up2 + (size_t)l * UH * F_DIM, b_up2 + (size_t)l * F_DIM,
            hn, N);
        float* t = hc; hc = hn; hn = t;
    }

    zero_kernel<<<(G * HID + 255) / 256, 256>>>(pooledp, G * HID);
    proj_pool_kernel<<<nblk, 256, PROJ_SMEM_BYTES>>>(
        hc, batch, Wp1, bp1, Wp2, bp2, pooledp, N);
    readout_kernel<<<(G + 63) / 64, 256, RO_SMEM_BYTES>>>(
        pooledp, Wr1, br1, Wr2, br2, out, G);
}

// round 15
// speedup vs baseline: 1.2919x; 1.1036x over previous
#include <cuda_runtime.h>
#include <cuda_fp16.h>
#include <cstdint>

#define F_DIM   128
#define FM_DIM  16
#define DIN     257
#define DH      514
#define UIN     144
#define UH      256
#define HID     128
#define T_OUT   12
#define SP      520     // padded row stride for Pd/Ps in HALVES (1040B, 16B-aligned)

#define MAXN 50048
#define MAXE 800000
#define MAXG 1024

// ---------------- scratch (no allocations allowed) ----------------
__device__ __align__(256) float  g_h0[MAXN * F_DIM];
__device__ __align__(256) float  g_h1[MAXN * F_DIM];
__device__ __align__(256) float  g_en2[MAXE];      // norm2, dst-sorted order
__device__ __align__(256) float  g_en2r[MAXE];     // norm2, raw edge order
__device__ __align__(256) float  g_agg[MAXN * FM_DIM];
__device__ __align__(256) float  g_pooled[MAXG * HID];
__device__ __align__(256) __half g_Pd[MAXN * SP];  // h @ W1[0:128] + b1   (fp16)
__device__ __align__(256) __half g_Ps[MAXN * SP];  // h @ W1[128:256]      (fp16)
__device__ __align__(256) int    g_cur[MAXN];      // scan cursor
__device__ __align__(256) int    g_es[MAXE];       // sorted src
__device__ __align__(256) int    g_ed[MAXE];       // sorted dst

// ---------------- helpers ----------------
__device__ __forceinline__ float swishf(float x) {
    return __fdividef(x, 1.0f + __expf(-x));
}

typedef unsigned long long ull;

__device__ __forceinline__ void fma2(ull& d, ull a, ull b) {
    asm("fma.rn.f32x2 %0, %1, %2, %0;" : "+l"(d) : "l"(a), "l"(b));
}
__device__ __forceinline__ ull pack2(float x) {
    ull r;
    asm("mov.b64 %0, {%1, %1};" : "=l"(r) : "f"(x));
    return r;
}
__device__ __forceinline__ void unpack2(ull v, float& lo, float& hi) {
    asm("mov.b64 {%0, %1}, %2;" : "=f"(lo), "=f"(hi) : "l"(v));
}

// ---------------- small kernels ----------------
__global__ void zero_kernel(float* p, int n) {
    int i = blockIdx.x * blockDim.x + threadIdx.x;
    if (i < n) p[i] = 0.0f;
}

// h init (+ zero the sort cursor, fused to save a launch)
__global__ void init_h_kernel(const void* zptr, const float* __restrict__ emb,
                              float* __restrict__ h, int* __restrict__ cur, int N) {
    int i = blockIdx.x * blockDim.x + threadIdx.x;
    if (i < N) cur[i] = 0;
    if (i >= N * F_DIM) return;
    int node = i / F_DIM, f = i % F_DIM;
    const int* z32 = (const int*)zptr;
    bool is64 = (z32[1] == 0) && (z32[3] == 0) && (z32[5] == 0);
    long long zv = is64 ? ((const long long*)zptr)[node] : (long long)z32[node];
    int e = (zv == 1) ? 0 : (int)(zv - 5);
    h[i] = emb[e * F_DIM + f];
}

__global__ void norm2_kernel(const float* __restrict__ pos,
                             const int* __restrict__ ei,
                             float* __restrict__ norm2, int E) {
    int e = blockIdx.x * blockDim.x + threadIdx.x;
    if (e >= E) return;
    int s = ei[e], d = ei[E + e];
    float dx = pos[s * 3 + 0] - pos[d * 3 + 0];
    float dy = pos[s * 3 + 1] - pos[d * 3 + 1];
    float dz = pos[s * 3 + 2] - pos[d * 3 + 2];
    norm2[e] = dx * dx + dy * dy + dz * dz;
}

// ---------------- counting sort of edges by dst ----------------
__global__ void hist_kernel(const int* __restrict__ ei, int* __restrict__ cnt, int E) {
    int e = blockIdx.x * blockDim.x + threadIdx.x;
    if (e < E) atomicAdd(&cnt[ei[E + e]], 1);
}

__global__ void scan_kernel(int* __restrict__ cnt, int* __restrict__ cur, int N) {
    __shared__ int sdata[1024];
    __shared__ int carry_s;
    if (threadIdx.x == 0) carry_s = 0;
    __syncthreads();
    for (int base = 0; base < N; base += 1024) {
        int i = base + threadIdx.x;
        int v = (i < N) ? cnt[i] : 0;
        sdata[threadIdx.x] = v;
        __syncthreads();
        for (int ofs = 1; ofs < 1024; ofs <<= 1) {
            int t = (threadIdx.x >= ofs) ? sdata[threadIdx.x - ofs] : 0;
            __syncthreads();
            sdata[threadIdx.x] += t;
            __syncthreads();
        }
        int excl = sdata[threadIdx.x] - v + carry_s;
        if (i < N) cur[i] = excl;
        __syncthreads();
        if (threadIdx.x == 0) carry_s += sdata[1023];
        __syncthreads();
    }
}

__global__ void scatter_kernel(const int* __restrict__ ei,
                               const float* __restrict__ en2r,
                               int* __restrict__ cur,
                               int* __restrict__ es, int* __restrict__ ed,
                               float* __restrict__ en2, int E) {
    int e = blockIdx.x * blockDim.x + threadIdx.x;
    if (e >= E) return;
    int s = ei[e], d = ei[E + e];
    int p = atomicAdd(&cur[d], 1);
    es[p] = s; ed[p] = d;
    en2[p] = en2r[e];
}

// ---------------- per-node pre-GEMM: P = h @ W (+bias), fp16 out ----------
// 128-node x 128-col tile, 8x8 output per thread (f32x2).
// __launch_bounds__(256, 2) caps regs at 128 -> 2 CTA/SM (was 130 regs, 1 CTA).
#define PREP_SMEM_BYTES ((128 * 132 + 8 * 132) * 4)

__global__ __launch_bounds__(256, 2)
void prep_gemm_kernel(const float* __restrict__ h, const float* __restrict__ W1,
                      const float* __restrict__ bias,
                      __half* __restrict__ Pd, __half* __restrict__ Ps,
                      float* __restrict__ agg, int N) {
    extern __shared__ float sm[];
    float* sH = sm;              // 128 x 132
    float* sB = sH + 128 * 132;  // 8 x 132

    const int tid = threadIdx.x;
    const int n0 = blockIdx.x * 128;
    const int c0 = blockIdx.y * 128;
    const int which = blockIdx.z;
    const float* W = W1 + (size_t)which * 128 * DH;
    __half* P = which ? Ps : Pd;

    if (blockIdx.y == 0 && blockIdx.z == 0) {
        for (int i = blockIdx.x * 256 + tid; i < N * FM_DIM; i += gridDim.x * 256)
            agg[i] = 0.0f;
    }

    // load h tile [128 x 128] as float4
    for (int idx = tid; idx < 128 * 32; idx += 256) {
        int r = idx >> 5, c4 = (idx & 31) * 4;
        int node = n0 + r;
        float4 v = make_float4(0.f, 0.f, 0.f, 0.f);
        if (node < N) v = *(const float4*)(h + (size_t)node * F_DIM + c4);
        *(float4*)(sH + r * 132 + c4) = v;
    }
    __syncthreads();

    const int ty = tid >> 4, tx = tid & 15;
    const int r0 = ty * 8, ct = tx * 8;

    ull C[8][4];
    #pragma unroll
    for (int i = 0; i < 8; i++)
        #pragma unroll
        for (int j = 0; j < 4; j++) C[i][j] = 0;

    for (int k0 = 0; k0 < 128; k0 += 8) {
        #pragma unroll
        for (int it = 0; it < 4; it++) {
            int t = tid + it * 256;
            int kk = t >> 7, c = t & 127;
            int col = c0 + c;
            sB[kk * 132 + c] = (col < DH) ? W[(size_t)(k0 + kk) * DH + col] : 0.0f;
        }
        __syncthreads();
        #pragma unroll
        for (int kk = 0; kk < 8; kk++) {
            const float* bp = sB + kk * 132 + ct;
            ull b0 = *(const ull*)(bp);
            ull b1 = *(const ull*)(bp + 2);
            ull b2v = *(const ull*)(bp + 4);
            ull b3 = *(const ull*)(bp + 6);
            #pragma unroll
            for (int i = 0; i < 8; i++) {
                ull aa = pack2(sH[(r0 + i) * 132 + k0 + kk]);
                fma2(C[i][0], aa, b0); fma2(C[i][1], aa, b1);
                fma2(C[i][2], aa, b2v); fma2(C[i][3], aa, b3);
            }
        }
        __syncthreads();
    }

    #pragma unroll
    for (int i = 0; i < 8; i++) {
        int node = n0 + r0 + i;
        if (node >= N) continue;
        float v[8];
        unpack2(C[i][0], v[0], v[1]); unpack2(C[i][1], v[2], v[3]);
        unpack2(C[i][2], v[4], v[5]); unpack2(C[i][3], v[6], v[7]);
        int col0 = c0 + ct;
        __half* prow = P + (size_t)node * SP + col0;
        #pragma unroll
        for (int j = 0; j < 8; j++)
            v[j] += (which == 0 && col0 + j < DH) ? bias[col0 + j] : 0.0f;
        if (col0 + 8 <= DH) {
            __half2 h01 = __floats2half2_rn(v[0], v[1]);
            __half2 h23 = __floats2half2_rn(v[2], v[3]);
            __half2 h45 = __floats2half2_rn(v[4], v[5]);
            __half2 h67 = __floats2half2_rn(v[6], v[7]);
            uint4 st;
            st.x = *(unsigned*)&h01; st.y = *(unsigned*)&h23;
            st.z = *(unsigned*)&h45; st.w = *(unsigned*)&h67;
            *(uint4*)prow = st;
        } else {
            #pragma unroll
            for (int j = 0; j < 8; j++)
                if (col0 + j < SP)
                    prow[j] = __float2half_rn((col0 + j < DH) ? v[j] : 0.0f);
        }
    }
}

// ---------------- edge phase: 2 edges/thread, register-resident ----------
// W2-row broadcast LDS amortized over 2 edges; sorted edges mean the pair
// usually shares dst (merged Pd lines + merged epilogue atomics).
#define EDGE_SMEM_BYTES ((516 * 16 + 516) * 4)

__global__ __launch_bounds__(256)
void edge_kernel(const __half* __restrict__ Pd, const __half* __restrict__ Ps,
                 const float* __restrict__ Wn,   // W1 row 256 (norm2 row)
                 const float* __restrict__ W2, const float* __restrict__ b2,
                 const int* __restrict__ es, const int* __restrict__ ed,
                 const float* __restrict__ en2,
                 float* __restrict__ agg, int E) {
    extern __shared__ float sm[];
    float* sW2 = sm;               // 516 x 16 (rows >=514 zero)
    float* sWn = sW2 + 516 * 16;   // 516 (pad zero)

    const int tid = threadIdx.x;
    for (int i = tid; i < 516 * 16; i += 256) {
        int k = i >> 4;
        sW2[i] = (k < DH) ? W2[i] : 0.0f;
    }
    for (int i = tid; i < 516; i += 256)
        sWn[i] = (i < DH) ? Wn[i] : 0.0f;
    __syncthreads();

    const int e0 = (blockIdx.x * 256 + tid) * 2;
    const bool a0 = (e0 < E), a1 = (e0 + 1 < E);
    int d0 = 0, s0 = 0, d1 = 0, s1 = 0;
    float n20 = 0.0f, n21 = 0.0f;
    if (a0) { d0 = ed[e0]; s0 = es[e0]; n20 = en2[e0]; }
    if (a1) { d1 = ed[e0 + 1]; s1 = es[e0 + 1]; n21 = en2[e0 + 1]; }
    const __half* pd0 = Pd + (size_t)d0 * SP;
    const __half* ps0 = Ps + (size_t)s0 * SP;
    const __half* pd1 = Pd + (size_t)d1 * SP;
    const __half* ps1 = Ps + (size_t)s1 * SP;

    ull m0[8], m1[8];
    #pragma unroll
    for (int j = 0; j < 8; j++) { m0[j] = 0; m1[j] = 0; }

    // buffers: 2 slots of 8 halves per edge per array (chunk = 16 k)
    uint4 bd0[2], bs0[2], bd1[2], bs1[2];
    #pragma unroll
    for (int j = 0; j < 2; j++) {
        bd0[j] = *(const uint4*)(pd0 + j * 8);
        bs0[j] = *(const uint4*)(ps0 + j * 8);
        bd1[j] = *(const uint4*)(pd1 + j * 8);
        bs1[j] = *(const uint4*)(ps1 + j * 8);
    }

    for (int c = 0; c < 32; c++) {
        const int k0 = c * 16;
        #pragma unroll
        for (int j = 0; j < 2; j++) {
            const __half2* hd0 = (const __half2*)&bd0[j];
            const __half2* hs0 = (const __half2*)&bs0[j];
            const __half2* hd1 = (const __half2*)&bd1[j];
            const __half2* hs1 = (const __half2*)&bs1[j];
            float2 f00 = __half22float2(__hadd2(hd0[0], hs0[0]));
            float2 f01 = __half22float2(__hadd2(hd0[1], hs0[1]));
            float2 f02 = __half22float2(__hadd2(hd0[2], hs0[2]));
            float2 f03 = __half22float2(__hadd2(hd0[3], hs0[3]));
            float2 f10 = __half22float2(__hadd2(hd1[0], hs1[0]));
            float2 f11 = __half22float2(__hadd2(hd1[1], hs1[1]));
            float2 f12 = __half22float2(__hadd2(hd1[2], hs1[2]));
            float2 f13 = __half22float2(__hadd2(hd1[3], hs1[3]));
            // refill this slot for the next chunk (covered by GEMM below)
            if (c < 31) {
                int off = k0 + 16 + j * 8;
                bd0[j] = *(const uint4*)(pd0 + off);
                bs0[j] = *(const uint4*)(ps0 + off);
                bd1[j] = *(const uint4*)(pd1 + off);
                bs1[j] = *(const uint4*)(ps1 + off);
            }
            const int kb = k0 + j * 8;
            float4 wl = *(const float4*)(sWn + kb);
            float4 wh = *(const float4*)(sWn + kb + 4);
            float x0[8], x1[8];
            x0[0] = fmaf(n20, wl.x, f00.x); x0[1] = fmaf(n20, wl.y, f00.y);
            x0[2] = fmaf(n20, wl.z, f01.x); x0[3] = fmaf(n20, wl.w, f01.y);
            x0[4] = fmaf(n20, wh.x, f02.x); x0[5] = fmaf(n20, wh.y, f02.y);
            x0[6] = fmaf(n20, wh.z, f03.x); x0[7] = fmaf(n20, wh.w, f03.y);
            x1[0] = fmaf(n21, wl.x, f10.x); x1[1] = fmaf(n21, wl.y, f10.y);
            x1[2] = fmaf(n21, wl.z, f11.x); x1[3] = fmaf(n21, wl.w, f11.y);
            x1[4] = fmaf(n21, wh.x, f12.x); x1[5] = fmaf(n21, wh.y, f12.y);
            x1[6] = fmaf(n21, wh.z, f13.x); x1[7] = fmaf(n21, wh.w, f13.y);
            #pragma unroll
            for (int q = 0; q < 8; q++) {
                ull a0p = pack2(swishf(x0[q]));
                ull a1p = pack2(swishf(x1[q]));
                const float* wp = sW2 + (kb + q) * 16;
                float4 w0 = *(const float4*)(wp);
                float4 w1 = *(const float4*)(wp + 4);
                float4 w2v = *(const float4*)(wp + 8);
                float4 w3 = *(const float4*)(wp + 12);
                ull u0 = *(ull*)&w0, u1 = *((ull*)&w0 + 1);
                ull u2 = *(ull*)&w1, u3 = *((ull*)&w1 + 1);
                ull u4 = *(ull*)&w2v, u5 = *((ull*)&w2v + 1);
                ull u6 = *(ull*)&w3, u7 = *((ull*)&w3 + 1);
                fma2(m0[0], a0p, u0); fma2(m0[1], a0p, u1);
                fma2(m0[2], a0p, u2); fma2(m0[3], a0p, u3);
                fma2(m0[4], a0p, u4); fma2(m0[5], a0p, u5);
                fma2(m0[6], a0p, u6); fma2(m0[7], a0p, u7);
                fma2(m1[0], a1p, u0); fma2(m1[1], a1p, u1);
                fma2(m1[2], a1p, u2); fma2(m1[3], a1p, u3);
                fma2(m1[4], a1p, u4); fma2(m1[5], a1p, u5);
                fma2(m1[6], a1p, u6); fma2(m1[7], a1p, u7);
            }
        }
    }

    // tail k = 512..513
    {
        float2 t0 = __half22float2(__hadd2(*(__half2*)(pd0 + 512), *(__half2*)(ps0 + 512)));
        float2 t1 = __half22float2(__hadd2(*(__half2*)(pd1 + 512), *(__half2*)(ps1 + 512)));
        float w512 = sWn[512], w513 = sWn[513];
        float xe0[2] = { fmaf(n20, w512, t0.x), fmaf(n20, w513, t0.y) };
        float xe1[2] = { fmaf(n21, w512, t1.x), fmaf(n21, w513, t1.y) };
        #pragma unroll
        for (int q = 0; q < 2; q++) {
            ull a0p = pack2(swishf(xe0[q]));
            ull a1p = pack2(swishf(xe1[q]));
            const float* wp = sW2 + (512 + q) * 16;
            float4 w0 = *(const float4*)(wp);
            float4 w1 = *(const float4*)(wp + 4);
            float4 w2v = *(const float4*)(wp + 8);
            float4 w3 = *(const float4*)(wp + 12);
            ull u0 = *(ull*)&w0, u1 = *((ull*)&w0 + 1);
            ull u2 = *(ull*)&w1, u3 = *((ull*)&w1 + 1);
            ull u4 = *(ull*)&w2v, u5 = *((ull*)&w2v + 1);
            ull u6 = *(ull*)&w3, u7 = *((ull*)&w3 + 1);
            fma2(m0[0], a0p, u0); fma2(m0[1], a0p, u1);
            fma2(m0[2], a0p, u2); fma2(m0[3], a0p, u3);
            fma2(m0[4], a0p, u4); fma2(m0[5], a0p, u5);
            fma2(m0[6], a0p, u6); fma2(m0[7], a0p, u7);
            fma2(m1[0], a1p, u0); fma2(m1[1], a1p, u1);
            fma2(m1[2], a1p, u2); fma2(m1[3], a1p, u3);
            fma2(m1[4], a1p, u4); fma2(m1[5], a1p, u5);
            fma2(m1[6], a1p, u6); fma2(m1[7], a1p, u7);
        }
    }

    // epilogue: swish(m2 + b2) -> atomic scatter (merge when pair shares dst)
    if (a0 && a1 && d0 == d1) {
        float* ap = agg + (size_t)d0 * FM_DIM;
        #pragma unroll
        for (int j = 0; j < 8; j++) {
            float lo0, hi0, lo1, hi1;
            unpack2(m0[j], lo0, hi0);
            unpack2(m1[j], lo1, hi1);
            float b0v = b2[2 * j], b1v = b2[2 * j + 1];
            atomicAdd(ap + 2 * j,     swishf(lo0 + b0v) + swishf(lo1 + b0v));
            atomicAdd(ap + 2 * j + 1, swishf(hi0 + b1v) + swishf(hi1 + b1v));
        }
    } else {
        if (a0) {
            float* ap = agg + (size_t)d0 * FM_DIM;
            #pragma unroll
            for (int j = 0; j < 8; j++) {
                float lo, hi;
                unpack2(m0[j], lo, hi);
                atomicAdd(ap + 2 * j,     swishf(lo + b2[2 * j]));
                atomicAdd(ap + 2 * j + 1, swishf(hi + b2[2 * j + 1]));
            }
        }
        if (a1) {
            float* ap = agg + (size_t)d1 * FM_DIM;
            #pragma unroll
            for (int j = 0; j < 8; j++) {
                float lo, hi;
                unpack2(m1[j], lo, hi);
                atomicAdd(ap + 2 * j,     swishf(lo + b2[2 * j]));
                atomicAdd(ap + 2 * j + 1, swishf(hi + b2[2 * j + 1]));
            }
        }
    }
}

// ---------------- fused node update ----------------
#define SU_STR 148
#define NODE_SMEM_BYTES ((64 * SU_STR + 64 * 132 + 8 * 132) * 4)

__global__ __launch_bounds__(256)
void node_update_kernel(const float* __restrict__ h,
                        const float* __restrict__ agg,
                        const float* __restrict__ W1, const float* __restrict__ b1,
                        const float* __restrict__ W2, const float* __restrict__ b2,
                        float* __restrict__ hout, int N) {
    extern __shared__ float sm[];
    float* sU  = sm;
    float* sU1 = sU + 64 * SU_STR;
    float* sB  = sU1 + 64 * 132;

    const int tid = threadIdx.x;
    const int n0 = blockIdx.x * 64;

    for (int idx = tid; idx < 64 * UIN; idx += 256) {
        int r = idx / UIN, c = idx % UIN;
        int node = n0 + r;
        float v = 0.0f;
        if (node < N)
            v = (c < FM_DIM) ? agg[(size_t)node * FM_DIM + c]
                             : h[(size_t)node * F_DIM + (c - FM_DIM)];
        sU[r * SU_STR + c] = v;
    }
    __syncthreads();

    const int ty = tid >> 4, tx = tid & 15;
    const int r0 = ty * 4, ct = tx * 8;

    float C2[4][8];
    #pragma unroll
    for (int i = 0; i < 4; i++)
        #pragma unroll
        for (int j = 0; j < 8; j++) C2[i][j] = 0.0f;

    for (int c0 = 0; c0 < UH; c0 += 128) {
        float C1[4][8];
        #pragma unroll
        for (int i = 0; i < 4; i++)
            #pragma unroll
            for (int j = 0; j < 8; j++) C1[i][j] = 0.0f;

        for (int k0 = 0; k0 < UIN; k0 += 8) {
            #pragma unroll
            for (int it = 0; it < 4; it++) {
                int t = tid + it * 256;
                int kk = t >> 7, c = t & 127;
                sB[kk * 132 + c] = W1[(size_t)(k0 + kk) * UH + c0 + c];
            }
            __syncthreads();
            #pragma unroll
            for (int kk = 0; kk < 8; kk++) {
                float4 b0 = *(const float4*)(sB + kk * 132 + ct);
                float4 b1v = *(const float4*)(sB + kk * 132 + ct + 4);
                #pragma unroll
                for (int i = 0; i < 4; i++) {
                    float a = sU[(r0 + i) * SU_STR + k0 + kk];
                    C1[i][0] += a * b0.x; C1[i][1] += a * b0.y;
                    C1[i][2] += a * b0.z; C1[i][3] += a * b0.w;
                    C1[i][4] += a * b1v.x; C1[i][5] += a * b1v.y;
                    C1[i][6] += a * b1v.z; C1[i][7] += a * b1v.w;
                }
            }
            __syncthreads();
        }
        #pragma unroll
        for (int i = 0; i < 4; i++)
            #pragma unroll
            for (int j = 0; j < 8; j++)
                sU1[(r0 + i) * 132 + ct + j] = swishf(C1[i][j] + b1[c0 + ct + j]);
        __syncthreads();

        for (int k0 = 0; k0 < 128; k0 += 8) {
            #pragma unroll
            for (int it = 0; it < 4; it++) {
                int t = tid + it * 256;
                int kk = t >> 7, c = t & 127;
                sB[kk * 132 + c] = W2[(size_t)(c0 + k0 + kk) * F_DIM + c];
            }
            __syncthreads();
            #pragma unroll
            for (int kk = 0; kk < 8; kk++) {
                float4 b0 = *(const float4*)(sB + kk * 132 + ct);
                float4 b1v = *(const float4*)(sB + kk * 132 + ct + 4);
                #pragma unroll
                for (int i = 0; i < 4; i++) {
                    float a = sU1[(r0 + i) * 132 + k0 + kk];
                    C2[i][0] += a * b0.x; C2[i][1] += a * b0.y;
                    C2[i][2] += a * b0.z; C2[i][3] += a * b0.w;
                    C2[i][4] += a * b1v.x; C2[i][5] += a * b1v.y;
                    C2[i][6] += a * b1v.z; C2[i][7] += a * b1v.w;
                }
            }
            __syncthreads();
        }
    }

    #pragma unroll
    for (int i = 0; i < 4; i++) {
        int node = n0 + r0 + i;
        if (node < N) {
            #pragma unroll
            for (int j = 0; j < 8; j++)
                hout[(size_t)node * F_DIM + ct + j] =
                    C2[i][j] + b2[ct + j] + sU[(r0 + i) * SU_STR + FM_DIM + ct + j];
        }
    }
}

// ---------------- projection + sorted-batch pooling ----------------
#define PROJ_SMEM_BYTES ((64 * 132 * 2 + 8 * 132) * 4 + 64 * 4)

__global__ __launch_bounds__(256)
void proj_pool_kernel(const float* __restrict__ h,
                      const int* __restrict__ batch,
                      const float* __restrict__ Wp1, const float* __restrict__ bp1,
                      const float* __restrict__ Wp2, const float* __restrict__ bp2,
                      float* __restrict__ pooled, int N) {
    extern __shared__ float sm[];
    float* sH = sm;
    float* sG = sH + 64 * 132;
    float* sB = sG + 64 * 132;
    int* sBatch = (int*)(sB + 8 * 132);

    const int tid = threadIdx.x;
    const int n0 = blockIdx.x * 64;

    for (int idx = tid; idx < 64 * HID; idx += 256) {
        int r = idx >> 7, c = idx & 127;
        int node = n0 + r;
        sH[r * 132 + c] = (node < N) ? h[(size_t)node * F_DIM + c] : 0.0f;
    }
    if (tid < 64) {
        int node = n0 + tid;
        sBatch[tid] = (node < N) ? batch[node] : -1;
    }
    __syncthreads();

    const int ty = tid >> 4, tx = tid & 15;
    const int r0 = ty * 4, ct = tx * 8;

    float C1[4][8];
    #pragma unroll
    for (int i = 0; i < 4; i++)
        #pragma unroll
        for (int j = 0; j < 8; j++) C1[i][j] = 0.0f;

    for (int k0 = 0; k0 < HID; k0 += 8) {
        #pragma unroll
        for (int it = 0; it < 4; it++) {
            int t = tid + it * 256;
            int kk = t >> 7, c = t & 127;
            sB[kk * 132 + c] = Wp1[(size_t)(k0 + kk) * HID + c];
        }
        __syncthreads();
        #pragma unroll
        for (int kk = 0; kk < 8; kk++) {
            float4 b0 = *(const float4*)(sB + kk * 132 + ct);
            float4 b1v = *(const float4*)(sB + kk * 132 + ct + 4);
            #pragma unroll
            for (int i = 0; i < 4; i++) {
                float a = sH[(r0 + i) * 132 + k0 + kk];
                C1[i][0] += a * b0.x; C1[i][1] += a * b0.y;
                C1[i][2] += a * b0.z; C1[i][3] += a * b0.w;
                C1[i][4] += a * b1v.x; C1[i][5] += a * b1v.y;
                C1[i][6] += a * b1v.z; C1[i][7] += a * b1v.w;
            }
        }
        __syncthreads();
    }
    #pragma unroll
    for (int i = 0; i < 4; i++)
        #pragma unroll
        for (int j = 0; j < 8; j++)
            sG[(r0 + i) * 132 + ct + j] = swishf(C1[i][j] + bp1[ct + j]);
    __syncthreads();

    float C2[4][8];
    #pragma unroll
    for (int i = 0; i < 4; i++)
        #pragma unroll
        for (int j = 0; j < 8; j++) C2[i][j] = 0.0f;

    for (int k0 = 0; k0 < HID; k0 += 8) {
        #pragma unroll
        for (int it = 0; it < 4; it++) {
            int t = tid + it * 256;
            int kk = t >> 7, c = t & 127;
            sB[kk * 132 + c] = Wp2[(size_t)(k0 + kk) * HID + c];
        }
        __syncthreads();
        #pragma unroll
        for (int kk = 0; kk < 8; kk++) {
            float4 b0 = *(const float4*)(sB + kk * 132 + ct);
            float4 b1v = *(const float4*)(sB + kk * 132 + ct + 4);
            #pragma unroll
            for (int i = 0; i < 4; i++) {
                float a = sG[(r0 + i) * 132 + k0 + kk];
                C2[i][0] += a * b0.x; C2[i][1] += a * b0.y;
                C2[i][2] += a * b0.z; C2[i][3] += a * b0.w;
                C2[i][4] += a * b1v.x; C2[i][5] += a * b1v.y;
                C2[i][6] += a * b1v.z; C2[i][7] += a * b1v.w;
            }
        }
        __syncthreads();
    }
    #pragma unroll
    for (int i = 0; i < 4; i++)
        #pragma unroll
        for (int j = 0; j < 8; j++)
            sH[(r0 + i) * 132 + ct + j] = C2[i][j] + bp2[ct + j];
    __syncthreads();

    if (tid < HID) {
        int col = tid;
        int g = sBatch[0];
        float acc = 0.0f;
        for (int r = 0; r < 64; r++) {
            int gg = sBatch[r];
            if (gg != g) {
                if (g >= 0) atomicAdd(&pooled[(size_t)g * HID + col], acc);
                acc = 0.0f;
                g = gg;
            }
            acc += sH[r * 132 + col];
        }
        if (g >= 0) atomicAdd(&pooled[(size_t)g * HID + col], acc);
    }
}

// ---------------- readout ----------------
#define RO_SMEM_BYTES ((64 * 132 * 2 + 8 * 132) * 4)

__global__ __launch_bounds__(256)
void readout_kernel(const float* __restrict__ pooled,
                    const float* __restrict__ Wr1, const float* __restrict__ br1,
                    const float* __restrict__ Wr2, const float* __restrict__ br2,
                    float* __restrict__ out, int G) {
    extern __shared__ float sm[];
    float* sP = sm;
    float* sR = sP + 64 * 132;
    float* sB = sR + 64 * 132;

    const int tid = threadIdx.x;
    const int g0 = blockIdx.x * 64;

    for (int idx = tid; idx < 64 * HID; idx += 256) {
        int r = idx >> 7, c = idx & 127;
        int g = g0 + r;
        sP[r * 132 + c] = (g < G) ? pooled[(size_t)g * HID + c] : 0.0f;
    }
    __syncthreads();

    const int ty = tid >> 4, tx = tid & 15;
    const int r0 = ty * 4, ct = tx * 8;

    float C1[4][8];
    #pragma unroll
    for (int i = 0; i < 4; i++)
        #pragma unroll
        for (int j = 0; j < 8; j++) C1[i][j] = 0.0f;

    for (int k0 = 0; k0 < HID; k0 += 8) {
        #pragma unroll
        for (int it = 0; it < 4; it++) {
            int t = tid + it * 256;
            int kk = t >> 7, c = t & 127;
            sB[kk * 132 + c] = Wr1[(size_t)(k0 + kk) * HID + c];
        }
        __syncthreads();
        #pragma unroll
        for (int kk = 0; kk < 8; kk++) {
            float4 b0 = *(const float4*)(sB + kk * 132 + ct);
            float4 b1v = *(const float4*)(sB + kk * 132 + ct + 4);
            #pragma unroll
            for (int i = 0; i < 4; i++) {
                float a = sP[(r0 + i) * 132 + k0 + kk];
                C1[i][0] += a * b0.x; C1[i][1] += a * b0.y;
                C1[i][2] += a * b0.z; C1[i][3] += a * b0.w;
                C1[i][4] += a * b1v.x; C1[i][5] += a * b1v.y;
                C1[i][6] += a * b1v.z; C1[i][7] += a * b1v.w;
            }
        }
        __syncthreads();
    }
    #pragma unroll
    for (int i = 0; i < 4; i++)
        #pragma unroll
        for (int j = 0; j < 8; j++)
            sR[(r0 + i) * 132 + ct + j] = swishf(C1[i][j] + br1[ct + j]);
    __syncthreads();

    for (int idx = tid; idx < 64 * T_OUT; idx += 256) {
        int e = idx / T_OUT, t = idx % T_OUT;
        int g = g0 + e;
        if (g < G) {
            float acc = br2[t];
            #pragma unroll 4
            for (int k = 0; k < HID; k++)
                acc += sR[e * 132 + k] * Wr2[(size_t)k * T_OUT + t];
            out[(size_t)g * T_OUT + t] = acc;
        }
    }
}

// ---------------- launch ----------------
extern "C" void kernel_launch(void* const* d_in, const int* in_sizes, int n_in,
                              void* d_out, int out_size) {
    const float* pos    = (const float*)d_in[0];
    const void*  zptr   = d_in[1];
    const int*   ei     = (const int*)d_in[2];
    const int*   batch  = (const int*)d_in[3];
    const float* emb    = (const float*)d_in[4];
    const float* W_msg1 = (const float*)d_in[5];
    const float* b_msg1 = (const float*)d_in[6];
    const float* W_msg2 = (const float*)d_in[7];
    const float* b_msg2 = (const float*)d_in[8];
    const float* W_up1  = (const float*)d_in[9];
    const float* b_up1  = (const float*)d_in[10];
    const float* W_up2  = (const float*)d_in[11];
    const float* b_up2  = (const float*)d_in[12];
    const float* Wp1    = (const float*)d_in[13];
    const float* bp1    = (const float*)d_in[14];
    const float* Wp2    = (const float*)d_in[15];
    const float* bp2    = (const float*)d_in[16];
    const float* Wr1    = (const float*)d_in[17];
    const float* br1    = (const float*)d_in[18];
    const float* Wr2    = (const float*)d_in[19];
    const float* br2    = (const float*)d_in[20];
    float* out = (float*)d_out;

    const int N = in_sizes[0] / 3;
    const int E = in_sizes[2] / 2;
    const int L = in_sizes[5] / (DIN * DH);
    const int G = out_size / T_OUT;

    float *h0, *h1, *aggp, *pooledp, *en2p, *en2rp;
    __half *pdp, *psp;
    int *curp, *esp, *edp;
    cudaGetSymbolAddress((void**)&h0, g_h0);
    cudaGetSymbolAddress((void**)&h1, g_h1);
    cudaGetSymbolAddress((void**)&aggp, g_agg);
    cudaGetSymbolAddress((void**)&pooledp, g_pooled);
    cudaGetSymbolAddress((void**)&en2p, g_en2);
    cudaGetSymbolAddress((void**)&en2rp, g_en2r);
    cudaGetSymbolAddress((void**)&pdp, g_Pd);
    cudaGetSymbolAddress((void**)&psp, g_Ps);
    cudaGetSymbolAddress((void**)&curp, g_cur);
    cudaGetSymbolAddress((void**)&esp, g_es);
    cudaGetSymbolAddress((void**)&edp, g_ed);

    cudaFuncSetAttribute(edge_kernel,
                         cudaFuncAttributeMaxDynamicSharedMemorySize, EDGE_SMEM_BYTES);
    cudaFuncSetAttribute(prep_gemm_kernel,
                         cudaFuncAttributeMaxDynamicSharedMemorySize, PREP_SMEM_BYTES);
    cudaFuncSetAttribute(node_update_kernel,
                         cudaFuncAttributeMaxDynamicSharedMemorySize, NODE_SMEM_BYTES);
    cudaFuncSetAttribute(proj_pool_kernel,
                         cudaFuncAttributeMaxDynamicSharedMemorySize, PROJ_SMEM_BYTES);
    cudaFuncSetAttribute(readout_kernel,
                         cudaFuncAttributeMaxDynamicSharedMemorySize, RO_SMEM_BYTES);

    const int nblk = (N + 63) / 64;
    const dim3 prep_grid((N + 127) / 128, 5, 2);
    const int eblk = (E + 511) / 512;   // 2 edges per thread

    // ---- launch order puts prep_gemm at local index 3 (ncu -s 5 -c 1) ----
    init_h_kernel<<<(N * F_DIM + 255) / 256, 256>>>(zptr, emb, h0, curp, N);   // 0
    hist_kernel<<<(E + 255) / 256, 256>>>(ei, curp, E);                        // 1
    scan_kernel<<<1, 1024>>>(curp, curp, N);                                   // 2
    prep_gemm_kernel<<<prep_grid, 256, PREP_SMEM_BYTES>>>(                     // 3 <- profiled
        h0, W_msg1, b_msg1, pdp, psp, aggp, N);
    norm2_kernel<<<(E + 255) / 256, 256>>>(pos, ei, en2rp, E);                 // 4
    scatter_kernel<<<(E + 255) / 256, 256>>>(ei, en2rp, curp, esp, edp, en2p, E); // 5
    edge_kernel<<<eblk, 256, EDGE_SMEM_BYTES>>>(                               // 6
        pdp, psp, W_msg1 + (size_t)256 * DH, W_msg2, b_msg2,
        esp, edp, en2p, aggp, E);
    node_update_kernel<<<nblk, 256, NODE_SMEM_BYTES>>>(                        // 7
        h0, aggp, W_up1, b_up1, W_up2, b_up2, h1, N);

    float* hc = h1;
    float* hn = h0;
    for (int l = 1; l < L; l++) {
        const float* W1l = W_msg1 + (size_t)l * DIN * DH;
        prep_gemm_kernel<<<prep_grid, 256, PREP_SMEM_BYTES>>>(
            hc, W1l, b_msg1 + (size_t)l * DH, pdp, psp, aggp, N);
        edge_kernel<<<eblk, 256, EDGE_SMEM_BYTES>>>(
            pdp, psp, W1l + (size_t)256 * DH,
            W_msg2 + (size_t)l * DH * FM_DIM, b_msg2 + (size_t)l * FM_DIM,
            esp, edp, en2p, aggp, E);
        node_update_kernel<<<nblk, 256, NODE_SMEM_BYTES>>>(
            hc, aggp,
            W_up1 + (size_t)l * UIN * UH, b_up1 + (size_t)l * UH,
            W_up2 + (size_t)l * UH * F_DIM, b_up2 + (size_t)l * F_DIM,
            hn, N);
        float* t = hc; hc = hn; hn = t;
    }

    zero_kernel<<<(G * HID + 255) / 256, 256>>>(pooledp, G * HID);
    proj_pool_kernel<<<nblk, 256, PROJ_SMEM_BYTES>>>(
        hc, batch, Wp1, bp1, Wp2, bp2, pooledp, N);
    readout_kernel<<<(G + 63) / 64, 256, RO_SMEM_BYTES>>>(
        pooledp, Wr1, br1, Wr2, br2, out, G);
}